// round 10
// baseline (speedup 1.0000x reference)
#include <cuda_runtime.h>
#include <math.h>

#define N_NODES 100000
#define N_EDGES 1000000
#define HID 64
#define EDIM 32
#define NSTEPS 4

typedef unsigned long long u64;

// ---- packed f32x2 helpers (FFMA2: only reachable via PTX fma.rn.f32x2) ----
__device__ __forceinline__ u64 fma2(u64 a, u64 b, u64 c) {
    u64 d; asm("fma.rn.f32x2 %0, %1, %2, %3;" : "=l"(d) : "l"(a), "l"(b), "l"(c)); return d;
}
__device__ __forceinline__ u64 pack2(float lo, float hi) {
    u64 d; asm("mov.b64 %0, {%1, %2};" : "=l"(d) : "f"(lo), "f"(hi)); return d;
}
__device__ __forceinline__ void unpack2(u64 v, float& lo, float& hi) {
    asm("mov.b64 {%0, %1}, %2;" : "=f"(lo), "=f"(hi) : "l"(v));
}
__device__ __forceinline__ float fsigmoid(float x) {
    return __fdividef(1.f, 1.f + __expf(-x));
}
__device__ __forceinline__ float ftanh(float x) {
    float e = __expf(-2.f * x);
    return __fdividef(1.f - e, 1.f + e);
}

// -------- device scratch --------
__device__ __align__(128) float g_msg[(size_t)N_EDGES * HID];   // 256 MB (CSR-ordered)
__device__ __align__(128) float g_agg[(size_t)N_NODES * HID];   // 25.6 MB
__device__ __align__(128) float g_W1t[EDIM * HID];              // [k][h]
__device__ __align__(128) float g_W2t[HID * HID];               // [k2][d]
__device__ __align__(128) int g_count[N_NODES];                 // zeroed by scan after use
__device__ __align__(128) int g_rowstart[N_NODES + 1];
__device__ __align__(128) int g_cursor[N_NODES];
__device__ __align__(128) int g_src[N_EDGES];
__device__ __align__(128) int g_eperm[N_EDGES];

// -------- CSR build: histogram (g_count is zero from BSS init / prior scan) --
__global__ __launch_bounds__(256) void hist_kernel(const int* __restrict__ eidx) {
    int t = blockIdx.x * 256 + threadIdx.x;
    if (t >= N_EDGES) return;
    int dst = eidx[t];
    if ((unsigned)dst < N_NODES) atomicAdd(&g_count[dst], 1);
}

// -------- CSR build: exclusive scan; transposes MLP weights; re-zeroes g_count
__global__ __launch_bounds__(1024) void scan_kernel(
    const float* __restrict__ W1, const float* __restrict__ W2)
{
    for (int i = threadIdx.x; i < EDIM * HID; i += 1024) {
        int k = i >> 6, h = i & 63;
        g_W1t[i] = W1[h * EDIM + k];
    }
    for (int i = threadIdx.x; i < HID * HID; i += 1024) {
        int k = i >> 6, d = i & 63;
        g_W2t[i] = W2[d * HID + k];
    }

    __shared__ int s[1024];
    const int T = 1024;
    const int tid = threadIdx.x;
    const int chunk = (N_NODES + T - 1) / T;
    const int start = tid * chunk;
    int sum = 0;
    for (int i = 0; i < chunk; ++i) {
        int idx = start + i;
        if (idx < N_NODES) sum += g_count[idx];
    }
    s[tid] = sum;
    __syncthreads();
    for (int off = 1; off < T; off <<= 1) {
        int v = 0;
        if (tid >= off) v = s[tid - off];
        __syncthreads();
        if (tid >= off) s[tid] += v;
        __syncthreads();
    }
    int run = (tid == 0) ? 0 : s[tid - 1];
    for (int i = 0; i < chunk; ++i) {
        int idx = start + i;
        if (idx < N_NODES) {
            g_rowstart[idx] = run;
            g_cursor[idx]   = run;
            run += g_count[idx];
            g_count[idx] = 0;     // reset for next launch (same thread owns idx)
        }
    }
    if (tid == T - 1) g_rowstart[N_NODES] = run;
}

// -------- CSR build: bucket placement --------
__global__ __launch_bounds__(256) void place_kernel(const int* __restrict__ eidx) {
    int t = blockIdx.x * 256 + threadIdx.x;
    if (t >= N_EDGES) return;
    int dst = eidx[t];
    int src = eidx[N_EDGES + t];
    if ((unsigned)dst >= N_NODES || (unsigned)src >= N_NODES) { g_eperm[t] = 0; return; }
    int pos = atomicAdd(&g_cursor[dst], 1);
    g_src[pos] = src;
    g_eperm[t] = pos;
}

// -------- K1: msg MLP, 4 edges x 8 outputs per thread, 75 KB smem ------------
#define ET 128
#define EPAD 132
#define MSG_SMEM_FLOATS ((EDIM + HID) * EPAD + EDIM * HID + HID * HID)
#define MSG_SMEM_BYTES  (MSG_SMEM_FLOATS * 4)   // 75,264 B -> 2 CTAs/SM

__global__ __launch_bounds__(256, 2) void msg_kernel(
    const float* __restrict__ ea,
    const float* __restrict__ b1, const float* __restrict__ b2)
{
    extern __shared__ float sm[];
    float* attrT = sm;                   // [32][EPAD]
    float* hidT  = attrT + EDIM * EPAD;  // [64][EPAD]
    float* sW1   = hidT + HID * EPAD;    // [k][h]   32x64
    float* sW2   = sW1 + EDIM * HID;     // [k2][d]  64x64

    const int tid = threadIdx.x;
    const int ex = tid & 31;             // lane
    const int oy = tid >> 5;             // warp 0..7
    const int eb = blockIdx.x * ET;

    {
        const float4* w1p = reinterpret_cast<const float4*>(g_W1t);
        const float4* w2p = reinterpret_cast<const float4*>(g_W2t);
        float4* s1 = reinterpret_cast<float4*>(sW1);
        float4* s2 = reinterpret_cast<float4*>(sW2);
        for (int i = tid; i < (EDIM * HID) / 4; i += 256) s1[i] = w1p[i];
        for (int i = tid; i < (HID * HID) / 4; i += 256)  s2[i] = w2p[i];
    }
    const float4* ea4 = reinterpret_cast<const float4*>(ea);
    for (int i = tid; i < ET * 8; i += 256) {
        int e = i >> 3, k4 = i & 7;
        long long ge = (long long)eb + e;
        float4 v = (ge < N_EDGES) ? __ldg(&ea4[ge * 8 + k4]) : make_float4(0.f, 0.f, 0.f, 0.f);
        attrT[(4 * k4 + 0) * EPAD + e] = v.x;
        attrT[(4 * k4 + 1) * EPAD + e] = v.y;
        attrT[(4 * k4 + 2) * EPAD + e] = v.z;
        attrT[(4 * k4 + 3) * EPAD + e] = v.w;
    }
    __syncthreads();

    u64 acc[16];

    // ---- layer 1 ----
    {
        const u64* b1p = reinterpret_cast<const u64*>(b1);
        #pragma unroll
        for (int hp = 0; hp < 4; ++hp) {
            u64 b = __ldg(&b1p[oy * 4 + hp]);
            acc[hp] = acc[4 + hp] = acc[8 + hp] = acc[12 + hp] = b;
        }
        #pragma unroll 2
        for (int k = 0; k < EDIM; ++k) {
            float4 a = *reinterpret_cast<const float4*>(&attrT[k * EPAD + ex * 4]);
            const ulonglong2* wp = reinterpret_cast<const ulonglong2*>(&sW1[k * HID + oy * 8]);
            ulonglong2 wA = wp[0], wB = wp[1];
            u64 w0 = wA.x, w1 = wA.y, w2 = wB.x, w3 = wB.y;
            u64 a0 = pack2(a.x, a.x), a1 = pack2(a.y, a.y);
            u64 a2 = pack2(a.z, a.z), a3 = pack2(a.w, a.w);
            acc[0]  = fma2(a0, w0, acc[0]);  acc[1]  = fma2(a0, w1, acc[1]);
            acc[2]  = fma2(a0, w2, acc[2]);  acc[3]  = fma2(a0, w3, acc[3]);
            acc[4]  = fma2(a1, w0, acc[4]);  acc[5]  = fma2(a1, w1, acc[5]);
            acc[6]  = fma2(a1, w2, acc[6]);  acc[7]  = fma2(a1, w3, acc[7]);
            acc[8]  = fma2(a2, w0, acc[8]);  acc[9]  = fma2(a2, w1, acc[9]);
            acc[10] = fma2(a2, w2, acc[10]); acc[11] = fma2(a2, w3, acc[11]);
            acc[12] = fma2(a3, w0, acc[12]); acc[13] = fma2(a3, w1, acc[13]);
            acc[14] = fma2(a3, w2, acc[14]); acc[15] = fma2(a3, w3, acc[15]);
        }
        #pragma unroll
        for (int hp = 0; hp < 4; ++hp) {
            float l0, u0, l1, u1, l2, u2, l3, u3;
            unpack2(acc[hp],      l0, u0);
            unpack2(acc[4 + hp],  l1, u1);
            unpack2(acc[8 + hp],  l2, u2);
            unpack2(acc[12 + hp], l3, u3);
            float4 vlo = make_float4(fmaxf(l0, 0.f), fmaxf(l1, 0.f), fmaxf(l2, 0.f), fmaxf(l3, 0.f));
            float4 vhi = make_float4(fmaxf(u0, 0.f), fmaxf(u1, 0.f), fmaxf(u2, 0.f), fmaxf(u3, 0.f));
            int h = oy * 8 + 2 * hp;
            *reinterpret_cast<float4*>(&hidT[h * EPAD + ex * 4])       = vlo;
            *reinterpret_cast<float4*>(&hidT[(h + 1) * EPAD + ex * 4]) = vhi;
        }
    }
    __syncthreads();

    // ---- layer 2 ----
    {
        const u64* b2p = reinterpret_cast<const u64*>(b2);
        #pragma unroll
        for (int hp = 0; hp < 4; ++hp) {
            u64 b = __ldg(&b2p[oy * 4 + hp]);
            acc[hp] = acc[4 + hp] = acc[8 + hp] = acc[12 + hp] = b;
        }
        #pragma unroll 2
        for (int k2 = 0; k2 < HID; ++k2) {
            float4 a = *reinterpret_cast<const float4*>(&hidT[k2 * EPAD + ex * 4]);
            const ulonglong2* wp = reinterpret_cast<const ulonglong2*>(&sW2[k2 * HID + oy * 8]);
            ulonglong2 wA = wp[0], wB = wp[1];
            u64 w0 = wA.x, w1 = wA.y, w2 = wB.x, w3 = wB.y;
            u64 a0 = pack2(a.x, a.x), a1 = pack2(a.y, a.y);
            u64 a2 = pack2(a.z, a.z), a3 = pack2(a.w, a.w);
            acc[0]  = fma2(a0, w0, acc[0]);  acc[1]  = fma2(a0, w1, acc[1]);
            acc[2]  = fma2(a0, w2, acc[2]);  acc[3]  = fma2(a0, w3, acc[3]);
            acc[4]  = fma2(a1, w0, acc[4]);  acc[5]  = fma2(a1, w1, acc[5]);
            acc[6]  = fma2(a1, w2, acc[6]);  acc[7]  = fma2(a1, w3, acc[7]);
            acc[8]  = fma2(a2, w0, acc[8]);  acc[9]  = fma2(a2, w1, acc[9]);
            acc[10] = fma2(a2, w2, acc[10]); acc[11] = fma2(a2, w3, acc[11]);
            acc[12] = fma2(a3, w0, acc[12]); acc[13] = fma2(a3, w1, acc[13]);
            acc[14] = fma2(a3, w2, acc[14]); acc[15] = fma2(a3, w3, acc[15]);
        }
        #pragma unroll
        for (int e = 0; e < 4; ++e) {
            int ge = eb + ex * 4 + e;
            if (ge < N_EDGES) {
                int slot = g_eperm[ge];
                ulonglong2* op = reinterpret_cast<ulonglong2*>(&g_msg[(size_t)slot * HID + oy * 8]);
                op[0] = make_ulonglong2(acc[e * 4 + 0], acc[e * 4 + 1]);
                op[1] = make_ulonglong2(acc[e * 4 + 2], acc[e * 4 + 3]);
            }
        }
    }
}

// -------- K2: gather aggregation (no atomics; streaming reads of g_msg) ------
__global__ __launch_bounds__(256) void gather_kernel(const float* __restrict__ h) {
    int t = blockIdx.x * 256 + threadIdx.x;
    int n = t >> 4;
    int q = t & 15;
    if (n >= N_NODES) return;
    int p  = g_rowstart[n];
    int re = g_rowstart[n + 1];
    float4 acc = make_float4(0.f, 0.f, 0.f, 0.f);
    for (; p + 1 < re; p += 2) {
        float4 m0 = __ldcs(reinterpret_cast<const float4*>(&g_msg[(size_t)p * HID + q * 4]));
        float4 m1 = __ldcs(reinterpret_cast<const float4*>(&g_msg[(size_t)(p + 1) * HID + q * 4]));
        int s0 = __ldg(&g_src[p]);
        int s1 = __ldg(&g_src[p + 1]);
        float4 h0 = __ldg(reinterpret_cast<const float4*>(&h[(size_t)s0 * HID + q * 4]));
        float4 h1 = __ldg(reinterpret_cast<const float4*>(&h[(size_t)s1 * HID + q * 4]));
        acc.x += m0.x * h0.x; acc.y += m0.y * h0.y; acc.z += m0.z * h0.z; acc.w += m0.w * h0.w;
        acc.x += m1.x * h1.x; acc.y += m1.y * h1.y; acc.z += m1.z * h1.z; acc.w += m1.w * h1.w;
    }
    if (p < re) {
        float4 m = __ldcs(reinterpret_cast<const float4*>(&g_msg[(size_t)p * HID + q * 4]));
        int s = __ldg(&g_src[p]);
        float4 hv = __ldg(reinterpret_cast<const float4*>(&h[(size_t)s * HID + q * 4]));
        acc.x += m.x * hv.x; acc.y += m.y * hv.y; acc.z += m.z * hv.z; acc.w += m.w * hv.w;
    }
    *reinterpret_cast<float4*>(&g_agg[(size_t)n * HID + q * 4]) = acc;
}

// -------- K3: GRU, k-paired FFMA2 (acc lanes = even/odd-k partials) ----------
// Weights [192][WKP] (pitch 68 -> conflict-free 4-phase LDS.128); data node-
// major [64][64] so per k-quad each node needs one broadcast LDS.128 per array.
// Per k-quad per warp: 6 weight LDS.128 + 16 broadcast LDS.128 + 96 FFMA2,
// zero packs. Bias folded in at the epilogue (lanes are k-partials).
#define WKP 68
#define GRU_TILE 64
#define GRU_SMEM_FLOATS (2 * 192 * WKP + 2 * GRU_TILE * HID)
#define GRU_SMEM_BYTES  (GRU_SMEM_FLOATS * 4)   // 137,216 B -> 1 CTA/SM

__global__ __launch_bounds__(512) void gru_kernel(
    const float* __restrict__ Wih, const float* __restrict__ bih,
    const float* __restrict__ Whh, const float* __restrict__ bhh,
    float* __restrict__ h)
{
    extern __shared__ float sm[];
    float* sWih = sm;                      // [192][WKP]
    float* sWhh = sWih + 192 * WKP;
    float* sAgg = sWhh + 192 * WKP;        // [64 nodes][64 k]
    float* sH   = sAgg + GRU_TILE * HID;

    const int tid = threadIdx.x;
    const int d = tid & 63;
    const int g = tid >> 6;                // 0..7, nodes g*8..g*8+7

    for (int i = tid; i < 192 * 64; i += 512) {
        int r = i >> 6, c = i & 63;
        sWih[r * WKP + c] = Wih[i];
        sWhh[r * WKP + c] = Whh[i];
    }
    const float bi_r = __ldg(&bih[d]), bi_z = __ldg(&bih[64 + d]), bi_n = __ldg(&bih[128 + d]);
    const float bh_r = __ldg(&bhh[d]), bh_z = __ldg(&bhh[64 + d]), bh_n = __ldg(&bhh[128 + d]);
    __syncthreads();

    const float* wr_i = &sWih[d * WKP];
    const float* wz_i = &sWih[(64 + d) * WKP];
    const float* wn_i = &sWih[(128 + d) * WKP];
    const float* wr_h = &sWhh[d * WKP];
    const float* wz_h = &sWhh[(64 + d) * WKP];
    const float* wn_h = &sWhh[(128 + d) * WKP];

    const int ntiles = (N_NODES + GRU_TILE - 1) / GRU_TILE;
    for (int tile = blockIdx.x; tile < ntiles; tile += gridDim.x) {
        const int nb = tile * GRU_TILE;
        // stage node-major (linear float4 copies)
        {
            const float4* ga = reinterpret_cast<const float4*>(&g_agg[(size_t)nb * 64]);
            const float4* gh = reinterpret_cast<const float4*>(&h[(size_t)nb * 64]);
            float4* sa = reinterpret_cast<float4*>(sAgg);
            float4* sh = reinterpret_cast<float4*>(sH);
            const size_t lim4 = ((size_t)N_NODES * 64 - (size_t)nb * 64) / 4;
            for (int i = tid; i < GRU_TILE * 16; i += 512) {
                bool ok = (size_t)i < lim4;
                sa[i] = ok ? ga[i] : make_float4(0.f, 0.f, 0.f, 0.f);
                sh[i] = ok ? gh[i] : make_float4(0.f, 0.f, 0.f, 0.f);
            }
        }
        __syncthreads();

        u64 acc_r[8], acc_z[8], acc_in[8], acc_hn[8];
        #pragma unroll
        for (int j = 0; j < 8; ++j) {
            acc_r[j] = 0ULL; acc_z[j] = 0ULL; acc_in[j] = 0ULL; acc_hn[j] = 0ULL;
        }

        #pragma unroll 2
        for (int kq = 0; kq < 64; kq += 4) {
            ulonglong2 wir = *reinterpret_cast<const ulonglong2*>(wr_i + kq);
            ulonglong2 wiz = *reinterpret_cast<const ulonglong2*>(wz_i + kq);
            ulonglong2 win = *reinterpret_cast<const ulonglong2*>(wn_i + kq);
            ulonglong2 whr = *reinterpret_cast<const ulonglong2*>(wr_h + kq);
            ulonglong2 whz = *reinterpret_cast<const ulonglong2*>(wz_h + kq);
            ulonglong2 whn = *reinterpret_cast<const ulonglong2*>(wn_h + kq);
            #pragma unroll
            for (int j = 0; j < 8; ++j) {
                ulonglong2 a  = *reinterpret_cast<const ulonglong2*>(&sAgg[(g * 8 + j) * 64 + kq]);
                ulonglong2 hh = *reinterpret_cast<const ulonglong2*>(&sH[(g * 8 + j) * 64 + kq]);
                acc_r[j]  = fma2(wir.x, a.x,  acc_r[j]);
                acc_r[j]  = fma2(wir.y, a.y,  acc_r[j]);
                acc_r[j]  = fma2(whr.x, hh.x, acc_r[j]);
                acc_r[j]  = fma2(whr.y, hh.y, acc_r[j]);
                acc_z[j]  = fma2(wiz.x, a.x,  acc_z[j]);
                acc_z[j]  = fma2(wiz.y, a.y,  acc_z[j]);
                acc_z[j]  = fma2(whz.x, hh.x, acc_z[j]);
                acc_z[j]  = fma2(whz.y, hh.y, acc_z[j]);
                acc_in[j] = fma2(win.x, a.x,  acc_in[j]);
                acc_in[j] = fma2(win.y, a.y,  acc_in[j]);
                acc_hn[j] = fma2(whn.x, hh.x, acc_hn[j]);
                acc_hn[j] = fma2(whn.y, hh.y, acc_hn[j]);
            }
        }

        #pragma unroll
        for (int j = 0; j < 8; ++j) {
            int n = g * 8 + j;
            if (nb + n < N_NODES) {
                float lo, hi;
                unpack2(acc_r[j], lo, hi);  float pr = lo + hi + bi_r + bh_r;
                unpack2(acc_z[j], lo, hi);  float pz = lo + hi + bi_z + bh_z;
                unpack2(acc_in[j], lo, hi); float pin = lo + hi + bi_n;
                unpack2(acc_hn[j], lo, hi); float phn = lo + hi + bh_n;
                float rv  = fsigmoid(pr);
                float zv  = fsigmoid(pz);
                float nnv = ftanh(pin + rv * phn);
                float hp  = sH[n * 64 + d];
                h[(size_t)(nb + n) * 64 + d] = (1.f - zv) * nnv + zv * hp;
            }
        }
        __syncthreads();
    }
}

// -------- launch --------
extern "C" void kernel_launch(void* const* d_in, const int* in_sizes, int n_in,
                              void* d_out, int out_size)
{
    const float* h0   = (const float*)d_in[0];
    const float* ea   = (const float*)d_in[1];
    const int*   eidx = (const int*)d_in[2];     // int64 inputs arrive as int32
    const float* W1   = (const float*)d_in[3];
    const float* b1   = (const float*)d_in[4];
    const float* W2   = (const float*)d_in[5];
    const float* b2   = (const float*)d_in[6];
    const float* Wih  = (const float*)d_in[7];
    const float* bih  = (const float*)d_in[8];
    const float* Whh  = (const float*)d_in[9];
    const float* bhh  = (const float*)d_in[10];
    float* h = (float*)d_out;

    cudaFuncSetAttribute(gru_kernel, cudaFuncAttributeMaxDynamicSharedMemorySize,
                         GRU_SMEM_BYTES);
    cudaFuncSetAttribute(msg_kernel, cudaFuncAttributeMaxDynamicSharedMemorySize,
                         MSG_SMEM_BYTES);

    cudaMemcpyAsync(h, h0, (size_t)N_NODES * HID * sizeof(float),
                    cudaMemcpyDeviceToDevice, 0);

    // CSR build; g_count re-zeroed inside scan_kernel (no memset launch)
    hist_kernel<<<(N_EDGES + 255) / 256, 256>>>(eidx);
    scan_kernel<<<1, 1024>>>(W1, W2);
    place_kernel<<<(N_EDGES + 255) / 256, 256>>>(eidx);

    msg_kernel<<<(N_EDGES + ET - 1) / ET, 256, MSG_SMEM_BYTES>>>(ea, b1, b2);

    // launch slot 6 -> ncu (-s 5 -c 1) captures the FIRST gather this round
    for (int s = 0; s < NSTEPS; ++s) {
        gather_kernel<<<(N_NODES * 16 + 255) / 256, 256>>>(h);
        gru_kernel<<<152, 512, GRU_SMEM_BYTES>>>(Wih, bih, Whh, bhh, h);
    }
}

// round 11
// speedup vs baseline: 1.0009x; 1.0009x over previous
#include <cuda_runtime.h>
#include <math.h>

#define N_NODES 100000
#define N_EDGES 1000000
#define HID 64
#define EDIM 32
#define NSTEPS 4

typedef unsigned long long u64;

// ---- packed f32x2 helpers (FFMA2: only reachable via PTX fma.rn.f32x2) ----
__device__ __forceinline__ u64 fma2(u64 a, u64 b, u64 c) {
    u64 d; asm("fma.rn.f32x2 %0, %1, %2, %3;" : "=l"(d) : "l"(a), "l"(b), "l"(c)); return d;
}
__device__ __forceinline__ u64 pack2(float lo, float hi) {
    u64 d; asm("mov.b64 %0, {%1, %2};" : "=l"(d) : "f"(lo), "f"(hi)); return d;
}
__device__ __forceinline__ void unpack2(u64 v, float& lo, float& hi) {
    asm("mov.b64 {%0, %1}, %2;" : "=f"(lo), "=f"(hi) : "l"(v));
}
__device__ __forceinline__ float fsigmoid(float x) {
    return __fdividef(1.f, 1.f + __expf(-x));
}
__device__ __forceinline__ float ftanh(float x) {
    float e = __expf(-2.f * x);
    return __fdividef(1.f - e, 1.f + e);
}

// -------- device scratch --------
__device__ __align__(128) float g_msg[(size_t)N_EDGES * HID];   // 256 MB (CSR-ordered)
__device__ __align__(128) float g_agg[(size_t)N_NODES * HID];   // 25.6 MB
__device__ __align__(128) float g_W1t[EDIM * HID];              // [k][h]
__device__ __align__(128) float g_W2t[HID * HID];               // [k2][d]
__device__ __align__(128) int g_count[N_NODES];                 // zeroed by scan after use
__device__ __align__(128) int g_rowstart[N_NODES + 1];
__device__ __align__(128) int g_cursor[N_NODES];
__device__ __align__(128) int g_src[N_EDGES];
__device__ __align__(128) int g_eperm[N_EDGES];

// -------- CSR build: histogram (g_count zero from BSS init / prior scan) -----
__global__ __launch_bounds__(256) void hist_kernel(const int* __restrict__ eidx) {
    int t = blockIdx.x * 256 + threadIdx.x;
    if (t >= N_EDGES) return;
    int dst = eidx[t];
    if ((unsigned)dst < N_NODES) atomicAdd(&g_count[dst], 1);
}

// -------- CSR build: exclusive scan; transposes MLP weights; re-zeroes g_count
__global__ __launch_bounds__(1024) void scan_kernel(
    const float* __restrict__ W1, const float* __restrict__ W2)
{
    for (int i = threadIdx.x; i < EDIM * HID; i += 1024) {
        int k = i >> 6, h = i & 63;
        g_W1t[i] = W1[h * EDIM + k];
    }
    for (int i = threadIdx.x; i < HID * HID; i += 1024) {
        int k = i >> 6, d = i & 63;
        g_W2t[i] = W2[d * HID + k];
    }

    __shared__ int s[1024];
    const int T = 1024;
    const int tid = threadIdx.x;
    const int chunk = (N_NODES + T - 1) / T;
    const int start = tid * chunk;
    int sum = 0;
    for (int i = 0; i < chunk; ++i) {
        int idx = start + i;
        if (idx < N_NODES) sum += g_count[idx];
    }
    s[tid] = sum;
    __syncthreads();
    for (int off = 1; off < T; off <<= 1) {
        int v = 0;
        if (tid >= off) v = s[tid - off];
        __syncthreads();
        if (tid >= off) s[tid] += v;
        __syncthreads();
    }
    int run = (tid == 0) ? 0 : s[tid - 1];
    for (int i = 0; i < chunk; ++i) {
        int idx = start + i;
        if (idx < N_NODES) {
            g_rowstart[idx] = run;
            g_cursor[idx]   = run;
            run += g_count[idx];
            g_count[idx] = 0;     // reset for next launch (same thread owns idx)
        }
    }
    if (tid == T - 1) g_rowstart[N_NODES] = run;
}

// -------- CSR build: bucket placement --------
__global__ __launch_bounds__(256) void place_kernel(const int* __restrict__ eidx) {
    int t = blockIdx.x * 256 + threadIdx.x;
    if (t >= N_EDGES) return;
    int dst = eidx[t];
    int src = eidx[N_EDGES + t];
    if ((unsigned)dst >= N_NODES || (unsigned)src >= N_NODES) { g_eperm[t] = 0; return; }
    int pos = atomicAdd(&g_cursor[dst], 1);
    g_src[pos] = src;
    g_eperm[t] = pos;
}

// -------- K1: msg MLP, 4 edges x 8 outputs per thread, 75 KB smem ------------
// 3 CTAs/SM (225,792 B total, fits 228 KB; regs <= 84 via launch bounds).
#define ET 128
#define EPAD 132
#define MSG_SMEM_FLOATS ((EDIM + HID) * EPAD + EDIM * HID + HID * HID)
#define MSG_SMEM_BYTES  (MSG_SMEM_FLOATS * 4)   // 75,264 B

__global__ __launch_bounds__(256, 3) void msg_kernel(
    const float* __restrict__ ea,
    const float* __restrict__ b1, const float* __restrict__ b2)
{
    extern __shared__ float sm[];
    float* attrT = sm;                   // [32][EPAD]
    float* hidT  = attrT + EDIM * EPAD;  // [64][EPAD]
    float* sW1   = hidT + HID * EPAD;    // [k][h]   32x64
    float* sW2   = sW1 + EDIM * HID;     // [k2][d]  64x64

    const int tid = threadIdx.x;
    const int ex = tid & 31;             // lane
    const int oy = tid >> 5;             // warp 0..7
    const int eb = blockIdx.x * ET;

    {
        const float4* w1p = reinterpret_cast<const float4*>(g_W1t);
        const float4* w2p = reinterpret_cast<const float4*>(g_W2t);
        float4* s1 = reinterpret_cast<float4*>(sW1);
        float4* s2 = reinterpret_cast<float4*>(sW2);
        for (int i = tid; i < (EDIM * HID) / 4; i += 256) s1[i] = w1p[i];
        for (int i = tid; i < (HID * HID) / 4; i += 256)  s2[i] = w2p[i];
    }
    const float4* ea4 = reinterpret_cast<const float4*>(ea);
    for (int i = tid; i < ET * 8; i += 256) {
        int e = i >> 3, k4 = i & 7;
        long long ge = (long long)eb + e;
        float4 v = (ge < N_EDGES) ? __ldg(&ea4[ge * 8 + k4]) : make_float4(0.f, 0.f, 0.f, 0.f);
        attrT[(4 * k4 + 0) * EPAD + e] = v.x;
        attrT[(4 * k4 + 1) * EPAD + e] = v.y;
        attrT[(4 * k4 + 2) * EPAD + e] = v.z;
        attrT[(4 * k4 + 3) * EPAD + e] = v.w;
    }
    __syncthreads();

    u64 acc[16];

    // ---- layer 1 ----
    {
        const u64* b1p = reinterpret_cast<const u64*>(b1);
        #pragma unroll
        for (int hp = 0; hp < 4; ++hp) {
            u64 b = __ldg(&b1p[oy * 4 + hp]);
            acc[hp] = acc[4 + hp] = acc[8 + hp] = acc[12 + hp] = b;
        }
        #pragma unroll 2
        for (int k = 0; k < EDIM; ++k) {
            float4 a = *reinterpret_cast<const float4*>(&attrT[k * EPAD + ex * 4]);
            const ulonglong2* wp = reinterpret_cast<const ulonglong2*>(&sW1[k * HID + oy * 8]);
            ulonglong2 wA = wp[0], wB = wp[1];
            u64 w0 = wA.x, w1 = wA.y, w2 = wB.x, w3 = wB.y;
            u64 a0 = pack2(a.x, a.x), a1 = pack2(a.y, a.y);
            u64 a2 = pack2(a.z, a.z), a3 = pack2(a.w, a.w);
            acc[0]  = fma2(a0, w0, acc[0]);  acc[1]  = fma2(a0, w1, acc[1]);
            acc[2]  = fma2(a0, w2, acc[2]);  acc[3]  = fma2(a0, w3, acc[3]);
            acc[4]  = fma2(a1, w0, acc[4]);  acc[5]  = fma2(a1, w1, acc[5]);
            acc[6]  = fma2(a1, w2, acc[6]);  acc[7]  = fma2(a1, w3, acc[7]);
            acc[8]  = fma2(a2, w0, acc[8]);  acc[9]  = fma2(a2, w1, acc[9]);
            acc[10] = fma2(a2, w2, acc[10]); acc[11] = fma2(a2, w3, acc[11]);
            acc[12] = fma2(a3, w0, acc[12]); acc[13] = fma2(a3, w1, acc[13]);
            acc[14] = fma2(a3, w2, acc[14]); acc[15] = fma2(a3, w3, acc[15]);
        }
        #pragma unroll
        for (int hp = 0; hp < 4; ++hp) {
            float l0, u0, l1, u1, l2, u2, l3, u3;
            unpack2(acc[hp],      l0, u0);
            unpack2(acc[4 + hp],  l1, u1);
            unpack2(acc[8 + hp],  l2, u2);
            unpack2(acc[12 + hp], l3, u3);
            float4 vlo = make_float4(fmaxf(l0, 0.f), fmaxf(l1, 0.f), fmaxf(l2, 0.f), fmaxf(l3, 0.f));
            float4 vhi = make_float4(fmaxf(u0, 0.f), fmaxf(u1, 0.f), fmaxf(u2, 0.f), fmaxf(u3, 0.f));
            int h = oy * 8 + 2 * hp;
            *reinterpret_cast<float4*>(&hidT[h * EPAD + ex * 4])       = vlo;
            *reinterpret_cast<float4*>(&hidT[(h + 1) * EPAD + ex * 4]) = vhi;
        }
    }
    __syncthreads();

    // ---- layer 2 ----
    {
        const u64* b2p = reinterpret_cast<const u64*>(b2);
        #pragma unroll
        for (int hp = 0; hp < 4; ++hp) {
            u64 b = __ldg(&b2p[oy * 4 + hp]);
            acc[hp] = acc[4 + hp] = acc[8 + hp] = acc[12 + hp] = b;
        }
        #pragma unroll 2
        for (int k2 = 0; k2 < HID; ++k2) {
            float4 a = *reinterpret_cast<const float4*>(&hidT[k2 * EPAD + ex * 4]);
            const ulonglong2* wp = reinterpret_cast<const ulonglong2*>(&sW2[k2 * HID + oy * 8]);
            ulonglong2 wA = wp[0], wB = wp[1];
            u64 w0 = wA.x, w1 = wA.y, w2 = wB.x, w3 = wB.y;
            u64 a0 = pack2(a.x, a.x), a1 = pack2(a.y, a.y);
            u64 a2 = pack2(a.z, a.z), a3 = pack2(a.w, a.w);
            acc[0]  = fma2(a0, w0, acc[0]);  acc[1]  = fma2(a0, w1, acc[1]);
            acc[2]  = fma2(a0, w2, acc[2]);  acc[3]  = fma2(a0, w3, acc[3]);
            acc[4]  = fma2(a1, w0, acc[4]);  acc[5]  = fma2(a1, w1, acc[5]);
            acc[6]  = fma2(a1, w2, acc[6]);  acc[7]  = fma2(a1, w3, acc[7]);
            acc[8]  = fma2(a2, w0, acc[8]);  acc[9]  = fma2(a2, w1, acc[9]);
            acc[10] = fma2(a2, w2, acc[10]); acc[11] = fma2(a2, w3, acc[11]);
            acc[12] = fma2(a3, w0, acc[12]); acc[13] = fma2(a3, w1, acc[13]);
            acc[14] = fma2(a3, w2, acc[14]); acc[15] = fma2(a3, w3, acc[15]);
        }
        #pragma unroll
        for (int e = 0; e < 4; ++e) {
            int ge = eb + ex * 4 + e;
            if (ge < N_EDGES) {
                int slot = g_eperm[ge];
                ulonglong2* op = reinterpret_cast<ulonglong2*>(&g_msg[(size_t)slot * HID + oy * 8]);
                op[0] = make_ulonglong2(acc[e * 4 + 0], acc[e * 4 + 1]);
                op[1] = make_ulonglong2(acc[e * 4 + 2], acc[e * 4 + 3]);
            }
        }
    }
}

// -------- K2: gather aggregation (no atomics; streaming reads of g_msg) ------
__global__ __launch_bounds__(256) void gather_kernel(const float* __restrict__ h) {
    int t = blockIdx.x * 256 + threadIdx.x;
    int n = t >> 4;
    int q = t & 15;
    if (n >= N_NODES) return;
    int p  = g_rowstart[n];
    int re = g_rowstart[n + 1];
    float4 acc = make_float4(0.f, 0.f, 0.f, 0.f);
    for (; p + 1 < re; p += 2) {
        float4 m0 = __ldcs(reinterpret_cast<const float4*>(&g_msg[(size_t)p * HID + q * 4]));
        float4 m1 = __ldcs(reinterpret_cast<const float4*>(&g_msg[(size_t)(p + 1) * HID + q * 4]));
        int s0 = __ldg(&g_src[p]);
        int s1 = __ldg(&g_src[p + 1]);
        float4 h0 = __ldg(reinterpret_cast<const float4*>(&h[(size_t)s0 * HID + q * 4]));
        float4 h1 = __ldg(reinterpret_cast<const float4*>(&h[(size_t)s1 * HID + q * 4]));
        acc.x += m0.x * h0.x; acc.y += m0.y * h0.y; acc.z += m0.z * h0.z; acc.w += m0.w * h0.w;
        acc.x += m1.x * h1.x; acc.y += m1.y * h1.y; acc.z += m1.z * h1.z; acc.w += m1.w * h1.w;
    }
    if (p < re) {
        float4 m = __ldcs(reinterpret_cast<const float4*>(&g_msg[(size_t)p * HID + q * 4]));
        int s = __ldg(&g_src[p]);
        float4 hv = __ldg(reinterpret_cast<const float4*>(&h[(size_t)s * HID + q * 4]));
        acc.x += m.x * hv.x; acc.y += m.y * hv.y; acc.z += m.z * hv.z; acc.w += m.w * hv.w;
    }
    *reinterpret_cast<float4*>(&g_agg[(size_t)n * HID + q * 4]) = acc;
}

// -------- K3: GRU via f32x2, node-pair accumulators (R9 winner, reverted) ----
#define WPAD 67
#define DPAD 68
#define GRU_TILE 64
#define GRU_SMEM_FLOATS (2 * 192 * WPAD + 2 * GRU_TILE * DPAD)
#define GRU_SMEM_BYTES  (GRU_SMEM_FLOATS * 4)

__global__ __launch_bounds__(512) void gru_kernel(
    const float* __restrict__ Wih, const float* __restrict__ bih,
    const float* __restrict__ Whh, const float* __restrict__ bhh,
    float* __restrict__ h)
{
    extern __shared__ float sm[];
    float* sWih  = sm;                        // [192][WPAD]
    float* sWhh  = sWih + 192 * WPAD;
    float* sAggT = sWhh + 192 * WPAD;         // [64][DPAD]
    float* sHT   = sAggT + GRU_TILE * DPAD;

    const int tid = threadIdx.x;
    const int d = tid & 63;
    const int g = tid >> 6;

    for (int i = tid; i < 192 * 64; i += 512) {
        int r = i >> 6, c = i & 63;
        sWih[r * WPAD + c] = Wih[i];
        sWhh[r * WPAD + c] = Whh[i];
    }
    const float bi_r = __ldg(&bih[d]), bi_z = __ldg(&bih[64 + d]), bi_n = __ldg(&bih[128 + d]);
    const float bh_r = __ldg(&bhh[d]), bh_z = __ldg(&bhh[64 + d]), bh_n = __ldg(&bhh[128 + d]);
    const u64 brz2 = pack2(bi_r + bh_r, bi_r + bh_r);
    const u64 bzz2 = pack2(bi_z + bh_z, bi_z + bh_z);
    const u64 bin2 = pack2(bi_n, bi_n);
    const u64 bhn2 = pack2(bh_n, bh_n);
    __syncthreads();

    const int ntiles = (N_NODES + GRU_TILE - 1) / GRU_TILE;
    for (int tile = blockIdx.x; tile < ntiles; tile += gridDim.x) {
        const int nb = tile * GRU_TILE;
        for (int i = tid; i < GRU_TILE * 64; i += 512) {
            int node = i >> 6, k = i & 63;
            bool ok = (nb + node) < N_NODES;
            size_t gi = (size_t)(nb + node) * 64 + k;
            sAggT[k * DPAD + node] = ok ? g_agg[gi] : 0.f;
            sHT[k * DPAD + node]   = ok ? h[gi] : 0.f;
        }
        __syncthreads();

        u64 acc_r[4], acc_z[4], acc_in[4], acc_hn[4];
        #pragma unroll
        for (int jp = 0; jp < 4; ++jp) {
            acc_r[jp] = brz2; acc_z[jp] = bzz2; acc_in[jp] = bin2; acc_hn[jp] = bhn2;
        }

        #pragma unroll 2
        for (int k = 0; k < 64; ++k) {
            float wir = sWih[d * WPAD + k];
            float wiz = sWih[(64 + d) * WPAD + k];
            float win = sWih[(128 + d) * WPAD + k];
            float whr = sWhh[d * WPAD + k];
            float whz = sWhh[(64 + d) * WPAD + k];
            float whn = sWhh[(128 + d) * WPAD + k];
            u64 wir2 = pack2(wir, wir), wiz2 = pack2(wiz, wiz), win2 = pack2(win, win);
            u64 whr2 = pack2(whr, whr), whz2 = pack2(whz, whz), whn2 = pack2(whn, whn);
            const ulonglong2* aT = reinterpret_cast<const ulonglong2*>(&sAggT[k * DPAD + g * 8]);
            const ulonglong2* hT = reinterpret_cast<const ulonglong2*>(&sHT[k * DPAD + g * 8]);
            #pragma unroll
            for (int jq = 0; jq < 2; ++jq) {
                ulonglong2 aa = aT[jq];
                ulonglong2 hh = hT[jq];
                acc_r[2*jq]   = fma2(wir2, aa.x, acc_r[2*jq]);
                acc_r[2*jq]   = fma2(whr2, hh.x, acc_r[2*jq]);
                acc_z[2*jq]   = fma2(wiz2, aa.x, acc_z[2*jq]);
                acc_z[2*jq]   = fma2(whz2, hh.x, acc_z[2*jq]);
                acc_in[2*jq]  = fma2(win2, aa.x, acc_in[2*jq]);
                acc_hn[2*jq]  = fma2(whn2, hh.x, acc_hn[2*jq]);
                acc_r[2*jq+1] = fma2(wir2, aa.y, acc_r[2*jq+1]);
                acc_r[2*jq+1] = fma2(whr2, hh.y, acc_r[2*jq+1]);
                acc_z[2*jq+1] = fma2(wiz2, aa.y, acc_z[2*jq+1]);
                acc_z[2*jq+1] = fma2(whz2, hh.y, acc_z[2*jq+1]);
                acc_in[2*jq+1]= fma2(win2, aa.y, acc_in[2*jq+1]);
                acc_hn[2*jq+1]= fma2(whn2, hh.y, acc_hn[2*jq+1]);
            }
        }

        #pragma unroll
        for (int jp = 0; jp < 4; ++jp) {
            float r0, r1, z0, z1, n0, n1, hn0, hn1;
            unpack2(acc_r[jp], r0, r1);
            unpack2(acc_z[jp], z0, z1);
            unpack2(acc_in[jp], n0, n1);
            unpack2(acc_hn[jp], hn0, hn1);
            int na = g * 8 + 2 * jp;
            #pragma unroll
            for (int half = 0; half < 2; ++half) {
                int n = na + half;
                if (nb + n < N_NODES) {
                    float rv  = fsigmoid(half ? r1 : r0);
                    float zv  = fsigmoid(half ? z1 : z0);
                    float nnv = ftanh((half ? n1 : n0) + rv * (half ? hn1 : hn0));
                    float hp  = sHT[d * DPAD + n];
                    h[(size_t)(nb + n) * 64 + d] = (1.f - zv) * nnv + zv * hp;
                }
            }
        }
        __syncthreads();
    }
}

// -------- launch --------
extern "C" void kernel_launch(void* const* d_in, const int* in_sizes, int n_in,
                              void* d_out, int out_size)
{
    const float* h0   = (const float*)d_in[0];
    const float* ea   = (const float*)d_in[1];
    const int*   eidx = (const int*)d_in[2];     // int64 inputs arrive as int32
    const float* W1   = (const float*)d_in[3];
    const float* b1   = (const float*)d_in[4];
    const float* W2   = (const float*)d_in[5];
    const float* b2   = (const float*)d_in[6];
    const float* Wih  = (const float*)d_in[7];
    const float* bih  = (const float*)d_in[8];
    const float* Whh  = (const float*)d_in[9];
    const float* bhh  = (const float*)d_in[10];
    float* h = (float*)d_out;

    cudaFuncSetAttribute(gru_kernel, cudaFuncAttributeMaxDynamicSharedMemorySize,
                         GRU_SMEM_BYTES);
    cudaFuncSetAttribute(msg_kernel, cudaFuncAttributeMaxDynamicSharedMemorySize,
                         MSG_SMEM_BYTES);

    cudaMemcpyAsync(h, h0, (size_t)N_NODES * HID * sizeof(float),
                    cudaMemcpyDeviceToDevice, 0);

    // CSR build; g_count re-zeroed inside scan_kernel (no memset launch)
    hist_kernel<<<(N_EDGES + 255) / 256, 256>>>(eidx);
    scan_kernel<<<1, 1024>>>(W1, W2);
    place_kernel<<<(N_EDGES + 255) / 256, 256>>>(eidx);

    msg_kernel<<<(N_EDGES + ET - 1) / ET, 256, MSG_SMEM_BYTES>>>(ea, b1, b2);

    for (int s = 0; s < NSTEPS; ++s) {
        gather_kernel<<<(N_NODES * 16 + 255) / 256, 256>>>(h);
        gru_kernel<<<152, 512, GRU_SMEM_BYTES>>>(Wih, bih, Whh, bhh, h);
    }
}

// round 12
// speedup vs baseline: 1.0116x; 1.0106x over previous
#include <cuda_runtime.h>
#include <cuda_bf16.h>
#include <math.h>

#define N_NODES 100000
#define N_EDGES 1000000
#define HID 64
#define EDIM 32
#define NSTEPS 4

typedef unsigned long long u64;

// ---- packed f32x2 helpers (FFMA2: only reachable via PTX fma.rn.f32x2) ----
__device__ __forceinline__ u64 fma2(u64 a, u64 b, u64 c) {
    u64 d; asm("fma.rn.f32x2 %0, %1, %2, %3;" : "=l"(d) : "l"(a), "l"(b), "l"(c)); return d;
}
__device__ __forceinline__ u64 pack2(float lo, float hi) {
    u64 d; asm("mov.b64 %0, {%1, %2};" : "=l"(d) : "f"(lo), "f"(hi)); return d;
}
__device__ __forceinline__ void unpack2(u64 v, float& lo, float& hi) {
    asm("mov.b64 {%0, %1}, %2;" : "=f"(lo), "=f"(hi) : "l"(v));
}
__device__ __forceinline__ float fsigmoid(float x) {
    return __fdividef(1.f, 1.f + __expf(-x));
}
__device__ __forceinline__ float ftanh(float x) {
    float e = __expf(-2.f * x);
    return __fdividef(1.f - e, 1.f + e);
}

// -------- device scratch --------
__device__ __align__(128) __nv_bfloat16 g_msgb[(size_t)N_EDGES * HID]; // 128 MB (CSR-ordered)
__device__ __align__(128) float g_agg[(size_t)N_NODES * HID];   // 25.6 MB
__device__ __align__(128) float g_W1t[EDIM * HID];              // [k][h]
__device__ __align__(128) float g_W2t[HID * HID];               // [k2][d]
__device__ __align__(128) int g_count[N_NODES];                 // zeroed by scan after use
__device__ __align__(128) int g_rowstart[N_NODES + 1];
__device__ __align__(128) int g_cursor[N_NODES];
__device__ __align__(128) int g_src[N_EDGES];
__device__ __align__(128) int g_eperm[N_EDGES];

// -------- CSR build: histogram (g_count zero from BSS init / prior scan) -----
__global__ __launch_bounds__(256) void hist_kernel(const int* __restrict__ eidx) {
    int t = blockIdx.x * 256 + threadIdx.x;
    if (t >= N_EDGES) return;
    int dst = eidx[t];
    if ((unsigned)dst < N_NODES) atomicAdd(&g_count[dst], 1);
}

// -------- CSR build: exclusive scan; transposes MLP weights; re-zeroes g_count
__global__ __launch_bounds__(1024) void scan_kernel(
    const float* __restrict__ W1, const float* __restrict__ W2)
{
    for (int i = threadIdx.x; i < EDIM * HID; i += 1024) {
        int k = i >> 6, h = i & 63;
        g_W1t[i] = W1[h * EDIM + k];
    }
    for (int i = threadIdx.x; i < HID * HID; i += 1024) {
        int k = i >> 6, d = i & 63;
        g_W2t[i] = W2[d * HID + k];
    }

    __shared__ int s[1024];
    const int T = 1024;
    const int tid = threadIdx.x;
    const int chunk = (N_NODES + T - 1) / T;
    const int start = tid * chunk;
    int sum = 0;
    for (int i = 0; i < chunk; ++i) {
        int idx = start + i;
        if (idx < N_NODES) sum += g_count[idx];
    }
    s[tid] = sum;
    __syncthreads();
    for (int off = 1; off < T; off <<= 1) {
        int v = 0;
        if (tid >= off) v = s[tid - off];
        __syncthreads();
        if (tid >= off) s[tid] += v;
        __syncthreads();
    }
    int run = (tid == 0) ? 0 : s[tid - 1];
    for (int i = 0; i < chunk; ++i) {
        int idx = start + i;
        if (idx < N_NODES) {
            g_rowstart[idx] = run;
            g_cursor[idx]   = run;
            run += g_count[idx];
            g_count[idx] = 0;     // reset for next launch (same thread owns idx)
        }
    }
    if (tid == T - 1) g_rowstart[N_NODES] = run;
}

// -------- CSR build: bucket placement --------
__global__ __launch_bounds__(256) void place_kernel(const int* __restrict__ eidx) {
    int t = blockIdx.x * 256 + threadIdx.x;
    if (t >= N_EDGES) return;
    int dst = eidx[t];
    int src = eidx[N_EDGES + t];
    if ((unsigned)dst >= N_NODES || (unsigned)src >= N_NODES) { g_eperm[t] = 0; return; }
    int pos = atomicAdd(&g_cursor[dst], 1);
    g_src[pos] = src;
    g_eperm[t] = pos;
}

// -------- K1: msg MLP, 4 edges x 8 outputs per thread; bf16 output ----------
#define ET 128
#define EPAD 132
#define MSG_SMEM_FLOATS ((EDIM + HID) * EPAD + EDIM * HID + HID * HID)
#define MSG_SMEM_BYTES  (MSG_SMEM_FLOATS * 4)   // 75,264 B -> 2 CTAs/SM

__global__ __launch_bounds__(256, 2) void msg_kernel(
    const float* __restrict__ ea,
    const float* __restrict__ b1, const float* __restrict__ b2)
{
    extern __shared__ float sm[];
    float* attrT = sm;                   // [32][EPAD]
    float* hidT  = attrT + EDIM * EPAD;  // [64][EPAD]
    float* sW1   = hidT + HID * EPAD;    // [k][h]   32x64
    float* sW2   = sW1 + EDIM * HID;     // [k2][d]  64x64

    const int tid = threadIdx.x;
    const int ex = tid & 31;             // lane
    const int oy = tid >> 5;             // warp 0..7
    const int eb = blockIdx.x * ET;

    {
        const float4* w1p = reinterpret_cast<const float4*>(g_W1t);
        const float4* w2p = reinterpret_cast<const float4*>(g_W2t);
        float4* s1 = reinterpret_cast<float4*>(sW1);
        float4* s2 = reinterpret_cast<float4*>(sW2);
        for (int i = tid; i < (EDIM * HID) / 4; i += 256) s1[i] = w1p[i];
        for (int i = tid; i < (HID * HID) / 4; i += 256)  s2[i] = w2p[i];
    }
    const float4* ea4 = reinterpret_cast<const float4*>(ea);
    for (int i = tid; i < ET * 8; i += 256) {
        int e = i >> 3, k4 = i & 7;
        long long ge = (long long)eb + e;
        float4 v = (ge < N_EDGES) ? __ldg(&ea4[ge * 8 + k4]) : make_float4(0.f, 0.f, 0.f, 0.f);
        attrT[(4 * k4 + 0) * EPAD + e] = v.x;
        attrT[(4 * k4 + 1) * EPAD + e] = v.y;
        attrT[(4 * k4 + 2) * EPAD + e] = v.z;
        attrT[(4 * k4 + 3) * EPAD + e] = v.w;
    }
    __syncthreads();

    u64 acc[16];

    // ---- layer 1 ----
    {
        const u64* b1p = reinterpret_cast<const u64*>(b1);
        #pragma unroll
        for (int hp = 0; hp < 4; ++hp) {
            u64 b = __ldg(&b1p[oy * 4 + hp]);
            acc[hp] = acc[4 + hp] = acc[8 + hp] = acc[12 + hp] = b;
        }
        #pragma unroll 2
        for (int k = 0; k < EDIM; ++k) {
            float4 a = *reinterpret_cast<const float4*>(&attrT[k * EPAD + ex * 4]);
            const ulonglong2* wp = reinterpret_cast<const ulonglong2*>(&sW1[k * HID + oy * 8]);
            ulonglong2 wA = wp[0], wB = wp[1];
            u64 w0 = wA.x, w1 = wA.y, w2 = wB.x, w3 = wB.y;
            u64 a0 = pack2(a.x, a.x), a1 = pack2(a.y, a.y);
            u64 a2 = pack2(a.z, a.z), a3 = pack2(a.w, a.w);
            acc[0]  = fma2(a0, w0, acc[0]);  acc[1]  = fma2(a0, w1, acc[1]);
            acc[2]  = fma2(a0, w2, acc[2]);  acc[3]  = fma2(a0, w3, acc[3]);
            acc[4]  = fma2(a1, w0, acc[4]);  acc[5]  = fma2(a1, w1, acc[5]);
            acc[6]  = fma2(a1, w2, acc[6]);  acc[7]  = fma2(a1, w3, acc[7]);
            acc[8]  = fma2(a2, w0, acc[8]);  acc[9]  = fma2(a2, w1, acc[9]);
            acc[10] = fma2(a2, w2, acc[10]); acc[11] = fma2(a2, w3, acc[11]);
            acc[12] = fma2(a3, w0, acc[12]); acc[13] = fma2(a3, w1, acc[13]);
            acc[14] = fma2(a3, w2, acc[14]); acc[15] = fma2(a3, w3, acc[15]);
        }
        #pragma unroll
        for (int hp = 0; hp < 4; ++hp) {
            float l0, u0, l1, u1, l2, u2, l3, u3;
            unpack2(acc[hp],      l0, u0);
            unpack2(acc[4 + hp],  l1, u1);
            unpack2(acc[8 + hp],  l2, u2);
            unpack2(acc[12 + hp], l3, u3);
            float4 vlo = make_float4(fmaxf(l0, 0.f), fmaxf(l1, 0.f), fmaxf(l2, 0.f), fmaxf(l3, 0.f));
            float4 vhi = make_float4(fmaxf(u0, 0.f), fmaxf(u1, 0.f), fmaxf(u2, 0.f), fmaxf(u3, 0.f));
            int h = oy * 8 + 2 * hp;
            *reinterpret_cast<float4*>(&hidT[h * EPAD + ex * 4])       = vlo;
            *reinterpret_cast<float4*>(&hidT[(h + 1) * EPAD + ex * 4]) = vhi;
        }
    }
    __syncthreads();

    // ---- layer 2 ----
    {
        const u64* b2p = reinterpret_cast<const u64*>(b2);
        #pragma unroll
        for (int hp = 0; hp < 4; ++hp) {
            u64 b = __ldg(&b2p[oy * 4 + hp]);
            acc[hp] = acc[4 + hp] = acc[8 + hp] = acc[12 + hp] = b;
        }
        #pragma unroll 2
        for (int k2 = 0; k2 < HID; ++k2) {
            float4 a = *reinterpret_cast<const float4*>(&hidT[k2 * EPAD + ex * 4]);
            const ulonglong2* wp = reinterpret_cast<const ulonglong2*>(&sW2[k2 * HID + oy * 8]);
            ulonglong2 wA = wp[0], wB = wp[1];
            u64 w0 = wA.x, w1 = wA.y, w2 = wB.x, w3 = wB.y;
            u64 a0 = pack2(a.x, a.x), a1 = pack2(a.y, a.y);
            u64 a2 = pack2(a.z, a.z), a3 = pack2(a.w, a.w);
            acc[0]  = fma2(a0, w0, acc[0]);  acc[1]  = fma2(a0, w1, acc[1]);
            acc[2]  = fma2(a0, w2, acc[2]);  acc[3]  = fma2(a0, w3, acc[3]);
            acc[4]  = fma2(a1, w0, acc[4]);  acc[5]  = fma2(a1, w1, acc[5]);
            acc[6]  = fma2(a1, w2, acc[6]);  acc[7]  = fma2(a1, w3, acc[7]);
            acc[8]  = fma2(a2, w0, acc[8]);  acc[9]  = fma2(a2, w1, acc[9]);
            acc[10] = fma2(a2, w2, acc[10]); acc[11] = fma2(a2, w3, acc[11]);
            acc[12] = fma2(a3, w0, acc[12]); acc[13] = fma2(a3, w1, acc[13]);
            acc[14] = fma2(a3, w2, acc[14]); acc[15] = fma2(a3, w3, acc[15]);
        }
        // store: edge row g_msgb[slot][oy*8 .. oy*8+7] as 8 bf16 = 16 B
        #pragma unroll
        for (int e = 0; e < 4; ++e) {
            int ge = eb + ex * 4 + e;
            if (ge < N_EDGES) {
                int slot = g_eperm[ge];
                float lo0, hi0, lo1, hi1, lo2, hi2, lo3, hi3;
                unpack2(acc[e * 4 + 0], lo0, hi0);
                unpack2(acc[e * 4 + 1], lo1, hi1);
                unpack2(acc[e * 4 + 2], lo2, hi2);
                unpack2(acc[e * 4 + 3], lo3, hi3);
                __nv_bfloat162 p0 = __floats2bfloat162_rn(lo0, hi0);
                __nv_bfloat162 p1 = __floats2bfloat162_rn(lo1, hi1);
                __nv_bfloat162 p2 = __floats2bfloat162_rn(lo2, hi2);
                __nv_bfloat162 p3 = __floats2bfloat162_rn(lo3, hi3);
                uint4 v = make_uint4(*(unsigned*)&p0, *(unsigned*)&p1,
                                     *(unsigned*)&p2, *(unsigned*)&p3);
                *reinterpret_cast<uint4*>(&g_msgb[(size_t)slot * HID + oy * 8]) = v;
            }
        }
    }
}

// -------- K2: gather aggregation (no atomics; bf16 msg stream, fp32 math) ----
__global__ __launch_bounds__(256) void gather_kernel(const float* __restrict__ h) {
    int t = blockIdx.x * 256 + threadIdx.x;
    int n = t >> 4;
    int q = t & 15;
    if (n >= N_NODES) return;
    int p  = g_rowstart[n];
    int re = g_rowstart[n + 1];
    float4 acc = make_float4(0.f, 0.f, 0.f, 0.f);
    for (; p + 1 < re; p += 2) {
        uint2 mb0 = __ldcs(reinterpret_cast<const uint2*>(&g_msgb[(size_t)p * HID + q * 4]));
        uint2 mb1 = __ldcs(reinterpret_cast<const uint2*>(&g_msgb[(size_t)(p + 1) * HID + q * 4]));
        int s0 = __ldg(&g_src[p]);
        int s1 = __ldg(&g_src[p + 1]);
        float4 h0 = __ldg(reinterpret_cast<const float4*>(&h[(size_t)s0 * HID + q * 4]));
        float4 h1 = __ldg(reinterpret_cast<const float4*>(&h[(size_t)s1 * HID + q * 4]));
        float2 a0 = __bfloat1622float2(*(__nv_bfloat162*)&mb0.x);
        float2 a1 = __bfloat1622float2(*(__nv_bfloat162*)&mb0.y);
        float2 b0 = __bfloat1622float2(*(__nv_bfloat162*)&mb1.x);
        float2 b1 = __bfloat1622float2(*(__nv_bfloat162*)&mb1.y);
        acc.x += a0.x * h0.x; acc.y += a0.y * h0.y; acc.z += a1.x * h0.z; acc.w += a1.y * h0.w;
        acc.x += b0.x * h1.x; acc.y += b0.y * h1.y; acc.z += b1.x * h1.z; acc.w += b1.y * h1.w;
    }
    if (p < re) {
        uint2 mb = __ldcs(reinterpret_cast<const uint2*>(&g_msgb[(size_t)p * HID + q * 4]));
        int s = __ldg(&g_src[p]);
        float4 hv = __ldg(reinterpret_cast<const float4*>(&h[(size_t)s * HID + q * 4]));
        float2 a0 = __bfloat1622float2(*(__nv_bfloat162*)&mb.x);
        float2 a1 = __bfloat1622float2(*(__nv_bfloat162*)&mb.y);
        acc.x += a0.x * hv.x; acc.y += a0.y * hv.y; acc.z += a1.x * hv.z; acc.w += a1.y * hv.w;
    }
    *reinterpret_cast<float4*>(&g_agg[(size_t)n * HID + q * 4]) = acc;
}

// -------- K3: GRU via f32x2, node-pair accumulators (R9 winner) --------------
#define WPAD 67
#define DPAD 68
#define GRU_TILE 64
#define GRU_SMEM_FLOATS (2 * 192 * WPAD + 2 * GRU_TILE * DPAD)
#define GRU_SMEM_BYTES  (GRU_SMEM_FLOATS * 4)

__global__ __launch_bounds__(512) void gru_kernel(
    const float* __restrict__ Wih, const float* __restrict__ bih,
    const float* __restrict__ Whh, const float* __restrict__ bhh,
    float* __restrict__ h)
{
    extern __shared__ float sm[];
    float* sWih  = sm;                        // [192][WPAD]
    float* sWhh  = sWih + 192 * WPAD;
    float* sAggT = sWhh + 192 * WPAD;         // [64][DPAD]
    float* sHT   = sAggT + GRU_TILE * DPAD;

    const int tid = threadIdx.x;
    const int d = tid & 63;
    const int g = tid >> 6;

    for (int i = tid; i < 192 * 64; i += 512) {
        int r = i >> 6, c = i & 63;
        sWih[r * WPAD + c] = Wih[i];
        sWhh[r * WPAD + c] = Whh[i];
    }
    const float bi_r = __ldg(&bih[d]), bi_z = __ldg(&bih[64 + d]), bi_n = __ldg(&bih[128 + d]);
    const float bh_r = __ldg(&bhh[d]), bh_z = __ldg(&bhh[64 + d]), bh_n = __ldg(&bhh[128 + d]);
    const u64 brz2 = pack2(bi_r + bh_r, bi_r + bh_r);
    const u64 bzz2 = pack2(bi_z + bh_z, bi_z + bh_z);
    const u64 bin2 = pack2(bi_n, bi_n);
    const u64 bhn2 = pack2(bh_n, bh_n);
    __syncthreads();

    const int ntiles = (N_NODES + GRU_TILE - 1) / GRU_TILE;
    for (int tile = blockIdx.x; tile < ntiles; tile += gridDim.x) {
        const int nb = tile * GRU_TILE;
        for (int i = tid; i < GRU_TILE * 64; i += 512) {
            int node = i >> 6, k = i & 63;
            bool ok = (nb + node) < N_NODES;
            size_t gi = (size_t)(nb + node) * 64 + k;
            sAggT[k * DPAD + node] = ok ? g_agg[gi] : 0.f;
            sHT[k * DPAD + node]   = ok ? h[gi] : 0.f;
        }
        __syncthreads();

        u64 acc_r[4], acc_z[4], acc_in[4], acc_hn[4];
        #pragma unroll
        for (int jp = 0; jp < 4; ++jp) {
            acc_r[jp] = brz2; acc_z[jp] = bzz2; acc_in[jp] = bin2; acc_hn[jp] = bhn2;
        }

        #pragma unroll 2
        for (int k = 0; k < 64; ++k) {
            float wir = sWih[d * WPAD + k];
            float wiz = sWih[(64 + d) * WPAD + k];
            float win = sWih[(128 + d) * WPAD + k];
            float whr = sWhh[d * WPAD + k];
            float whz = sWhh[(64 + d) * WPAD + k];
            float whn = sWhh[(128 + d) * WPAD + k];
            u64 wir2 = pack2(wir, wir), wiz2 = pack2(wiz, wiz), win2 = pack2(win, win);
            u64 whr2 = pack2(whr, whr), whz2 = pack2(whz, whz), whn2 = pack2(whn, whn);
            const ulonglong2* aT = reinterpret_cast<const ulonglong2*>(&sAggT[k * DPAD + g * 8]);
            const ulonglong2* hT = reinterpret_cast<const ulonglong2*>(&sHT[k * DPAD + g * 8]);
            #pragma unroll
            for (int jq = 0; jq < 2; ++jq) {
                ulonglong2 aa = aT[jq];
                ulonglong2 hh = hT[jq];
                acc_r[2*jq]   = fma2(wir2, aa.x, acc_r[2*jq]);
                acc_r[2*jq]   = fma2(whr2, hh.x, acc_r[2*jq]);
                acc_z[2*jq]   = fma2(wiz2, aa.x, acc_z[2*jq]);
                acc_z[2*jq]   = fma2(whz2, hh.x, acc_z[2*jq]);
                acc_in[2*jq]  = fma2(win2, aa.x, acc_in[2*jq]);
                acc_hn[2*jq]  = fma2(whn2, hh.x, acc_hn[2*jq]);
                acc_r[2*jq+1] = fma2(wir2, aa.y, acc_r[2*jq+1]);
                acc_r[2*jq+1] = fma2(whr2, hh.y, acc_r[2*jq+1]);
                acc_z[2*jq+1] = fma2(wiz2, aa.y, acc_z[2*jq+1]);
                acc_z[2*jq+1] = fma2(whz2, hh.y, acc_z[2*jq+1]);
                acc_in[2*jq+1]= fma2(win2, aa.y, acc_in[2*jq+1]);
                acc_hn[2*jq+1]= fma2(whn2, hh.y, acc_hn[2*jq+1]);
            }
        }

        #pragma unroll
        for (int jp = 0; jp < 4; ++jp) {
            float r0, r1, z0, z1, n0, n1, hn0, hn1;
            unpack2(acc_r[jp], r0, r1);
            unpack2(acc_z[jp], z0, z1);
            unpack2(acc_in[jp], n0, n1);
            unpack2(acc_hn[jp], hn0, hn1);
            int na = g * 8 + 2 * jp;
            #pragma unroll
            for (int half = 0; half < 2; ++half) {
                int n = na + half;
                if (nb + n < N_NODES) {
                    float rv  = fsigmoid(half ? r1 : r0);
                    float zv  = fsigmoid(half ? z1 : z0);
                    float nnv = ftanh((half ? n1 : n0) + rv * (half ? hn1 : hn0));
                    float hp  = sHT[d * DPAD + n];
                    h[(size_t)(nb + n) * 64 + d] = (1.f - zv) * nnv + zv * hp;
                }
            }
        }
        __syncthreads();
    }
}

// -------- launch --------
extern "C" void kernel_launch(void* const* d_in, const int* in_sizes, int n_in,
                              void* d_out, int out_size)
{
    const float* h0   = (const float*)d_in[0];
    const float* ea   = (const float*)d_in[1];
    const int*   eidx = (const int*)d_in[2];     // int64 inputs arrive as int32
    const float* W1   = (const float*)d_in[3];
    const float* b1   = (const float*)d_in[4];
    const float* W2   = (const float*)d_in[5];
    const float* b2   = (const float*)d_in[6];
    const float* Wih  = (const float*)d_in[7];
    const float* bih  = (const float*)d_in[8];
    const float* Whh  = (const float*)d_in[9];
    const float* bhh  = (const float*)d_in[10];
    float* h = (float*)d_out;

    cudaFuncSetAttribute(gru_kernel, cudaFuncAttributeMaxDynamicSharedMemorySize,
                         GRU_SMEM_BYTES);
    cudaFuncSetAttribute(msg_kernel, cudaFuncAttributeMaxDynamicSharedMemorySize,
                         MSG_SMEM_BYTES);

    cudaMemcpyAsync(h, h0, (size_t)N_NODES * HID * sizeof(float),
                    cudaMemcpyDeviceToDevice, 0);

    // CSR build; g_count re-zeroed inside scan_kernel (no memset launch)
    hist_kernel<<<(N_EDGES + 255) / 256, 256>>>(eidx);
    scan_kernel<<<1, 1024>>>(W1, W2);
    place_kernel<<<(N_EDGES + 255) / 256, 256>>>(eidx);

    msg_kernel<<<(N_EDGES + ET - 1) / ET, 256, MSG_SMEM_BYTES>>>(ea, b1, b2);

    for (int s = 0; s < NSTEPS; ++s) {
        gather_kernel<<<(N_NODES * 16 + 255) / 256, 256>>>(h);
        gru_kernel<<<152, 512, GRU_SMEM_BYTES>>>(Wih, bih, Whh, bhh, h);
    }
}

// round 13
// speedup vs baseline: 1.0698x; 1.0576x over previous
#include <cuda_runtime.h>
#include <math.h>

#define N_NODES 100000
#define N_EDGES 1000000
#define HID 64
#define EDIM 32
#define NSTEPS 4

typedef unsigned long long u64;
typedef unsigned int u32;

// ---- packed f32x2 helpers (FFMA2) ----
__device__ __forceinline__ u64 fma2(u64 a, u64 b, u64 c) {
    u64 d; asm("fma.rn.f32x2 %0, %1, %2, %3;" : "=l"(d) : "l"(a), "l"(b), "l"(c)); return d;
}
__device__ __forceinline__ u64 pack2(float lo, float hi) {
    u64 d; asm("mov.b64 %0, {%1, %2};" : "=l"(d) : "f"(lo), "f"(hi)); return d;
}
__device__ __forceinline__ void unpack2(u64 v, float& lo, float& hi) {
    asm("mov.b64 {%0, %1}, %2;" : "=f"(lo), "=f"(hi) : "l"(v));
}
__device__ __forceinline__ float fsigmoid(float x) {
    return __fdividef(1.f, 1.f + __expf(-x));
}
__device__ __forceinline__ float ftanh(float x) {
    float e = __expf(-2.f * x);
    return __fdividef(1.f - e, 1.f + e);
}
// ---- tf32 helpers ----
__device__ __forceinline__ u32 f2tf(float f) {
    u32 u; asm("cvt.rna.tf32.f32 %0, %1;" : "=r"(u) : "f"(f)); return u;
}
__device__ __forceinline__ void mma_tf32(float* c, u32 a0, u32 a1, u32 a2, u32 a3,
                                         u32 b0, u32 b1) {
    asm volatile("mma.sync.aligned.m16n8k8.row.col.f32.tf32.tf32.f32 "
        "{%0,%1,%2,%3}, {%4,%5,%6,%7}, {%8,%9}, {%0,%1,%2,%3};"
        : "+f"(c[0]), "+f"(c[1]), "+f"(c[2]), "+f"(c[3])
        : "r"(a0), "r"(a1), "r"(a2), "r"(a3), "r"(b0), "r"(b1));
}

// -------- device scratch --------
__device__ __align__(128) float g_msg[(size_t)N_EDGES * HID];   // 256 MB (CSR-ordered, fp32)
__device__ __align__(128) float g_agg[(size_t)N_NODES * HID];   // 25.6 MB
__device__ __align__(128) u32 g_W1frag[4 * 8 * 32 * 2];         // tf32 B-frags, layer 1
__device__ __align__(128) u32 g_W2frag[8 * 8 * 32 * 2];         // tf32 B-frags, layer 2
__device__ __align__(128) int g_count[N_NODES];                 // zeroed by scan after use
__device__ __align__(128) int g_rowstart[N_NODES + 1];
__device__ __align__(128) int g_cursor[N_NODES];
__device__ __align__(128) int g_src[N_EDGES];
__device__ __align__(128) int g_eperm[N_EDGES];

// -------- CSR build: histogram --------
__global__ __launch_bounds__(256) void hist_kernel(const int* __restrict__ eidx) {
    int t = blockIdx.x * 256 + threadIdx.x;
    if (t >= N_EDGES) return;
    int dst = eidx[t];
    if ((unsigned)dst < N_NODES) atomicAdd(&g_count[dst], 1);
}

// -------- CSR build: exclusive scan; builds tf32 weight fragments; re-zeroes g_count
__global__ __launch_bounds__(1024) void scan_kernel(
    const float* __restrict__ W1, const float* __restrict__ W2)
{
    // B-fragment layout for mma.m16n8k8: lane = g*4+t; b0=(k=kk*8+t, n=nt*8+g),
    // b1 = same with k+4. Stored at [((kk*8+nt)*32 + lane)*2 + {0,1}], tf32 bits.
    {
        int p = threadIdx.x;                 // 0..1023 = 4 kk * 8 nt * 32 lanes
        int lane = p & 31, nt = (p >> 5) & 7, kk = p >> 8;       // kk 0..3
        int gg = lane >> 2, tt = lane & 3;
        int n = nt * 8 + gg;                 // n = hidden index h
        g_W1frag[p * 2]     = f2tf(W1[n * EDIM + kk * 8 + tt]);
        g_W1frag[p * 2 + 1] = f2tf(W1[n * EDIM + kk * 8 + tt + 4]);
    }
    for (int p = threadIdx.x; p < 2048; p += 1024) {             // 8 kk * 8 nt * 32
        int lane = p & 31, nt = (p >> 5) & 7, kk = p >> 8;       // kk 0..7
        int gg = lane >> 2, tt = lane & 3;
        int n = nt * 8 + gg;                 // n = output dim d
        g_W2frag[p * 2]     = f2tf(W2[n * HID + kk * 8 + tt]);
        g_W2frag[p * 2 + 1] = f2tf(W2[n * HID + kk * 8 + tt + 4]);
    }

    __shared__ int s[1024];
    const int T = 1024;
    const int tid = threadIdx.x;
    const int chunk = (N_NODES + T - 1) / T;
    const int start = tid * chunk;
    int sum = 0;
    for (int i = 0; i < chunk; ++i) {
        int idx = start + i;
        if (idx < N_NODES) sum += g_count[idx];
    }
    s[tid] = sum;
    __syncthreads();
    for (int off = 1; off < T; off <<= 1) {
        int v = 0;
        if (tid >= off) v = s[tid - off];
        __syncthreads();
        if (tid >= off) s[tid] += v;
        __syncthreads();
    }
    int run = (tid == 0) ? 0 : s[tid - 1];
    for (int i = 0; i < chunk; ++i) {
        int idx = start + i;
        if (idx < N_NODES) {
            g_rowstart[idx] = run;
            g_cursor[idx]   = run;
            run += g_count[idx];
            g_count[idx] = 0;
        }
    }
    if (tid == T - 1) g_rowstart[N_NODES] = run;
}

// -------- CSR build: bucket placement --------
__global__ __launch_bounds__(256) void place_kernel(const int* __restrict__ eidx) {
    int t = blockIdx.x * 256 + threadIdx.x;
    if (t >= N_EDGES) return;
    int dst = eidx[t];
    int src = eidx[N_EDGES + t];
    if ((unsigned)dst >= N_NODES || (unsigned)src >= N_NODES) { g_eperm[t] = 0; return; }
    int pos = atomicAdd(&g_cursor[dst], 1);
    g_src[pos] = src;
    g_eperm[t] = pos;
}

// -------- K1: msg MLP via tf32 mma.sync (m16n8k8) ---------------------------
// CTA = 256 threads (8 warps) x 256 edges; warp owns 32 edges (2 m16-tiles),
// fully independent (hid round-trip is warp-private smem; __syncwarp only).
// A loaded per-lane from gmem (edge rows are 128B-aligned); B from pre-swizzled
// fragment arrays (conflict-free LDS.64); C init = bias; fp32 stores to g_msg.
#define MSG_PITCH 68   // words; banks (4g + t) all-distinct for frag reads
#define MSG_SMEM_WORDS (256 * MSG_PITCH + 2048 + 4096)
#define MSG_SMEM_BYTES (MSG_SMEM_WORDS * 4)   // 94,208 B -> 2 CTAs/SM

__global__ __launch_bounds__(256, 2) void msg_kernel(
    const float* __restrict__ ea,
    const float* __restrict__ b1, const float* __restrict__ b2)
{
    extern __shared__ u32 smu[];
    u32* hidS = smu;                     // [256 edges][MSG_PITCH] tf32 bits
    u32* f1   = smu + 256 * MSG_PITCH;   // 2048 u32
    u32* f2   = f1 + 2048;               // 4096 u32

    const int tid = threadIdx.x;
    const int w = tid >> 5;
    const int lane = tid & 31;
    const int g = lane >> 2, t = lane & 3;
    const int eb = blockIdx.x * 256;

    for (int i = tid; i < 2048; i += 256) f1[i] = g_W1frag[i];
    for (int i = tid; i < 4096; i += 256) f2[i] = g_W2frag[i];
    __syncthreads();

    const int ebase = eb + w * 32;

    #pragma unroll 1
    for (int m = 0; m < 2; ++m) {
        const int e0 = ebase + m * 16;
        const int r0 = e0 + g, r1 = e0 + g + 8;
        const int lr0 = w * 32 + m * 16 + g, lr1 = lr0 + 8;
        float c[8][4];

        // ---- layer 1: C[32x64] = A[32x32] * W1^T + b1 ----
        #pragma unroll
        for (int nt = 0; nt < 8; ++nt) {
            float blo = __ldg(&b1[nt * 8 + 2 * t]);
            float bhi = __ldg(&b1[nt * 8 + 2 * t + 1]);
            c[nt][0] = blo; c[nt][1] = bhi; c[nt][2] = blo; c[nt][3] = bhi;
        }
        #pragma unroll
        for (int kk = 0; kk < 4; ++kk) {
            float fa0 = (r0 < N_EDGES) ? __ldg(&ea[(size_t)r0 * EDIM + kk * 8 + t])     : 0.f;
            float fa1 = (r1 < N_EDGES) ? __ldg(&ea[(size_t)r1 * EDIM + kk * 8 + t])     : 0.f;
            float fa2 = (r0 < N_EDGES) ? __ldg(&ea[(size_t)r0 * EDIM + kk * 8 + t + 4]) : 0.f;
            float fa3 = (r1 < N_EDGES) ? __ldg(&ea[(size_t)r1 * EDIM + kk * 8 + t + 4]) : 0.f;
            u32 a0 = f2tf(fa0), a1 = f2tf(fa1), a2 = f2tf(fa2), a3 = f2tf(fa3);
            #pragma unroll
            for (int nt = 0; nt < 8; ++nt) {
                uint2 b = *reinterpret_cast<const uint2*>(&f1[((kk * 8 + nt) * 32 + lane) * 2]);
                mma_tf32(c[nt], a0, a1, a2, a3, b.x, b.y);
            }
        }
        // relu -> tf32 -> warp-private hid rows
        #pragma unroll
        for (int nt = 0; nt < 8; ++nt) {
            u32 v00 = f2tf(fmaxf(c[nt][0], 0.f)), v01 = f2tf(fmaxf(c[nt][1], 0.f));
            u32 v10 = f2tf(fmaxf(c[nt][2], 0.f)), v11 = f2tf(fmaxf(c[nt][3], 0.f));
            *reinterpret_cast<uint2*>(&hidS[lr0 * MSG_PITCH + nt * 8 + 2 * t]) = make_uint2(v00, v01);
            *reinterpret_cast<uint2*>(&hidS[lr1 * MSG_PITCH + nt * 8 + 2 * t]) = make_uint2(v10, v11);
        }
        __syncwarp();

        // ---- layer 2: C[32x64] = hid[32x64] * W2^T + b2 ----
        #pragma unroll
        for (int nt = 0; nt < 8; ++nt) {
            float blo = __ldg(&b2[nt * 8 + 2 * t]);
            float bhi = __ldg(&b2[nt * 8 + 2 * t + 1]);
            c[nt][0] = blo; c[nt][1] = bhi; c[nt][2] = blo; c[nt][3] = bhi;
        }
        #pragma unroll
        for (int kk = 0; kk < 8; ++kk) {
            u32 a0 = hidS[lr0 * MSG_PITCH + kk * 8 + t];
            u32 a1 = hidS[lr1 * MSG_PITCH + kk * 8 + t];
            u32 a2 = hidS[lr0 * MSG_PITCH + kk * 8 + t + 4];
            u32 a3 = hidS[lr1 * MSG_PITCH + kk * 8 + t + 4];
            #pragma unroll
            for (int nt = 0; nt < 8; ++nt) {
                uint2 b = *reinterpret_cast<const uint2*>(&f2[((kk * 8 + nt) * 32 + lane) * 2]);
                mma_tf32(c[nt], a0, a1, a2, a3, b.x, b.y);
            }
        }
        // store to CSR-permuted g_msg (fp32)
        int slot0 = (r0 < N_EDGES) ? __ldg(&g_eperm[r0]) : 0;
        int slot1 = (r1 < N_EDGES) ? __ldg(&g_eperm[r1]) : 0;
        #pragma unroll
        for (int nt = 0; nt < 8; ++nt) {
            if (r0 < N_EDGES)
                *reinterpret_cast<float2*>(&g_msg[(size_t)slot0 * HID + nt * 8 + 2 * t]) =
                    make_float2(c[nt][0], c[nt][1]);
            if (r1 < N_EDGES)
                *reinterpret_cast<float2*>(&g_msg[(size_t)slot1 * HID + nt * 8 + 2 * t]) =
                    make_float2(c[nt][2], c[nt][3]);
        }
        __syncwarp();
    }
}

// -------- K2: gather aggregation (no atomics; streaming fp32 msg) -----------
__global__ __launch_bounds__(256) void gather_kernel(const float* __restrict__ h) {
    int t = blockIdx.x * 256 + threadIdx.x;
    int n = t >> 4;
    int q = t & 15;
    if (n >= N_NODES) return;
    int p  = g_rowstart[n];
    int re = g_rowstart[n + 1];
    float4 acc = make_float4(0.f, 0.f, 0.f, 0.f);
    for (; p + 1 < re; p += 2) {
        float4 m0 = __ldcs(reinterpret_cast<const float4*>(&g_msg[(size_t)p * HID + q * 4]));
        float4 m1 = __ldcs(reinterpret_cast<const float4*>(&g_msg[(size_t)(p + 1) * HID + q * 4]));
        int s0 = __ldg(&g_src[p]);
        int s1 = __ldg(&g_src[p + 1]);
        float4 h0 = __ldg(reinterpret_cast<const float4*>(&h[(size_t)s0 * HID + q * 4]));
        float4 h1 = __ldg(reinterpret_cast<const float4*>(&h[(size_t)s1 * HID + q * 4]));
        acc.x += m0.x * h0.x; acc.y += m0.y * h0.y; acc.z += m0.z * h0.z; acc.w += m0.w * h0.w;
        acc.x += m1.x * h1.x; acc.y += m1.y * h1.y; acc.z += m1.z * h1.z; acc.w += m1.w * h1.w;
    }
    if (p < re) {
        float4 m = __ldcs(reinterpret_cast<const float4*>(&g_msg[(size_t)p * HID + q * 4]));
        int s = __ldg(&g_src[p]);
        float4 hv = __ldg(reinterpret_cast<const float4*>(&h[(size_t)s * HID + q * 4]));
        acc.x += m.x * hv.x; acc.y += m.y * hv.y; acc.z += m.z * hv.z; acc.w += m.w * hv.w;
    }
    *reinterpret_cast<float4*>(&g_agg[(size_t)n * HID + q * 4]) = acc;
}

// -------- K3: GRU via f32x2, node-pair accumulators (R9 winner) --------------
#define WPAD 67
#define DPAD 68
#define GRU_TILE 64
#define GRU_SMEM_FLOATS (2 * 192 * WPAD + 2 * GRU_TILE * DPAD)
#define GRU_SMEM_BYTES  (GRU_SMEM_FLOATS * 4)

__global__ __launch_bounds__(512) void gru_kernel(
    const float* __restrict__ Wih, const float* __restrict__ bih,
    const float* __restrict__ Whh, const float* __restrict__ bhh,
    float* __restrict__ h)
{
    extern __shared__ float sm[];
    float* sWih  = sm;                        // [192][WPAD]
    float* sWhh  = sWih + 192 * WPAD;
    float* sAggT = sWhh + 192 * WPAD;         // [64][DPAD]
    float* sHT   = sAggT + GRU_TILE * DPAD;

    const int tid = threadIdx.x;
    const int d = tid & 63;
    const int g = tid >> 6;

    for (int i = tid; i < 192 * 64; i += 512) {
        int r = i >> 6, c = i & 63;
        sWih[r * WPAD + c] = Wih[i];
        sWhh[r * WPAD + c] = Whh[i];
    }
    const float bi_r = __ldg(&bih[d]), bi_z = __ldg(&bih[64 + d]), bi_n = __ldg(&bih[128 + d]);
    const float bh_r = __ldg(&bhh[d]), bh_z = __ldg(&bhh[64 + d]), bh_n = __ldg(&bhh[128 + d]);
    const u64 brz2 = pack2(bi_r + bh_r, bi_r + bh_r);
    const u64 bzz2 = pack2(bi_z + bh_z, bi_z + bh_z);
    const u64 bin2 = pack2(bi_n, bi_n);
    const u64 bhn2 = pack2(bh_n, bh_n);
    __syncthreads();

    const int ntiles = (N_NODES + GRU_TILE - 1) / GRU_TILE;
    for (int tile = blockIdx.x; tile < ntiles; tile += gridDim.x) {
        const int nb = tile * GRU_TILE;
        for (int i = tid; i < GRU_TILE * 64; i += 512) {
            int node = i >> 6, k = i & 63;
            bool ok = (nb + node) < N_NODES;
            size_t gi = (size_t)(nb + node) * 64 + k;
            sAggT[k * DPAD + node] = ok ? g_agg[gi] : 0.f;
            sHT[k * DPAD + node]   = ok ? h[gi] : 0.f;
        }
        __syncthreads();

        u64 acc_r[4], acc_z[4], acc_in[4], acc_hn[4];
        #pragma unroll
        for (int jp = 0; jp < 4; ++jp) {
            acc_r[jp] = brz2; acc_z[jp] = bzz2; acc_in[jp] = bin2; acc_hn[jp] = bhn2;
        }

        #pragma unroll 2
        for (int k = 0; k < 64; ++k) {
            float wir = sWih[d * WPAD + k];
            float wiz = sWih[(64 + d) * WPAD + k];
            float win = sWih[(128 + d) * WPAD + k];
            float whr = sWhh[d * WPAD + k];
            float whz = sWhh[(64 + d) * WPAD + k];
            float whn = sWhh[(128 + d) * WPAD + k];
            u64 wir2 = pack2(wir, wir), wiz2 = pack2(wiz, wiz), win2 = pack2(win, win);
            u64 whr2 = pack2(whr, whr), whz2 = pack2(whz, whz), whn2 = pack2(whn, whn);
            const ulonglong2* aT = reinterpret_cast<const ulonglong2*>(&sAggT[k * DPAD + g * 8]);
            const ulonglong2* hT = reinterpret_cast<const ulonglong2*>(&sHT[k * DPAD + g * 8]);
            #pragma unroll
            for (int jq = 0; jq < 2; ++jq) {
                ulonglong2 aa = aT[jq];
                ulonglong2 hh = hT[jq];
                acc_r[2*jq]   = fma2(wir2, aa.x, acc_r[2*jq]);
                acc_r[2*jq]   = fma2(whr2, hh.x, acc_r[2*jq]);
                acc_z[2*jq]   = fma2(wiz2, aa.x, acc_z[2*jq]);
                acc_z[2*jq]   = fma2(whz2, hh.x, acc_z[2*jq]);
                acc_in[2*jq]  = fma2(win2, aa.x, acc_in[2*jq]);
                acc_hn[2*jq]  = fma2(whn2, hh.x, acc_hn[2*jq]);
                acc_r[2*jq+1] = fma2(wir2, aa.y, acc_r[2*jq+1]);
                acc_r[2*jq+1] = fma2(whr2, hh.y, acc_r[2*jq+1]);
                acc_z[2*jq+1] = fma2(wiz2, aa.y, acc_z[2*jq+1]);
                acc_z[2*jq+1] = fma2(whz2, hh.y, acc_z[2*jq+1]);
                acc_in[2*jq+1]= fma2(win2, aa.y, acc_in[2*jq+1]);
                acc_hn[2*jq+1]= fma2(whn2, hh.y, acc_hn[2*jq+1]);
            }
        }

        #pragma unroll
        for (int jp = 0; jp < 4; ++jp) {
            float r0, r1, z0, z1, n0, n1, hn0, hn1;
            unpack2(acc_r[jp], r0, r1);
            unpack2(acc_z[jp], z0, z1);
            unpack2(acc_in[jp], n0, n1);
            unpack2(acc_hn[jp], hn0, hn1);
            int na = g * 8 + 2 * jp;
            #pragma unroll
            for (int half = 0; half < 2; ++half) {
                int n = na + half;
                if (nb + n < N_NODES) {
                    float rv  = fsigmoid(half ? r1 : r0);
                    float zv  = fsigmoid(half ? z1 : z0);
                    float nnv = ftanh((half ? n1 : n0) + rv * (half ? hn1 : hn0));
                    float hp  = sHT[d * DPAD + n];
                    h[(size_t)(nb + n) * 64 + d] = (1.f - zv) * nnv + zv * hp;
                }
            }
        }
        __syncthreads();
    }
}

// -------- launch --------
extern "C" void kernel_launch(void* const* d_in, const int* in_sizes, int n_in,
                              void* d_out, int out_size)
{
    const float* h0   = (const float*)d_in[0];
    const float* ea   = (const float*)d_in[1];
    const int*   eidx = (const int*)d_in[2];     // int64 inputs arrive as int32
    const float* W1   = (const float*)d_in[3];
    const float* b1   = (const float*)d_in[4];
    const float* W2   = (const float*)d_in[5];
    const float* b2   = (const float*)d_in[6];
    const float* Wih  = (const float*)d_in[7];
    const float* bih  = (const float*)d_in[8];
    const float* Whh  = (const float*)d_in[9];
    const float* bhh  = (const float*)d_in[10];
    float* h = (float*)d_out;

    cudaFuncSetAttribute(gru_kernel, cudaFuncAttributeMaxDynamicSharedMemorySize,
                         GRU_SMEM_BYTES);
    cudaFuncSetAttribute(msg_kernel, cudaFuncAttributeMaxDynamicSharedMemorySize,
                         MSG_SMEM_BYTES);

    cudaMemcpyAsync(h, h0, (size_t)N_NODES * HID * sizeof(float),
                    cudaMemcpyDeviceToDevice, 0);

    // CSR build; g_count re-zeroed inside scan_kernel
    hist_kernel<<<(N_EDGES + 255) / 256, 256>>>(eidx);
    scan_kernel<<<1, 1024>>>(W1, W2);
    place_kernel<<<(N_EDGES + 255) / 256, 256>>>(eidx);

    msg_kernel<<<(N_EDGES + 255) / 256, 256, MSG_SMEM_BYTES>>>(ea, b1, b2);

    for (int s = 0; s < NSTEPS; ++s) {
        gather_kernel<<<(N_NODES * 16 + 255) / 256, 256>>>(h);
        gru_kernel<<<152, 512, GRU_SMEM_BYTES>>>(Wih, bih, Whh, bhh, h);
    }
}

// round 14
// speedup vs baseline: 1.1847x; 1.1075x over previous
#include <cuda_runtime.h>
#include <math.h>

#define N_NODES 100000
#define N_EDGES 1000000
#define HID 64
#define EDIM 32
#define NSTEPS 4

typedef unsigned long long u64;
typedef unsigned int u32;

__device__ __forceinline__ float fsigmoid(float x) {
    return __fdividef(1.f, 1.f + __expf(-x));
}
__device__ __forceinline__ float ftanh(float x) {
    float e = __expf(-2.f * x);
    return __fdividef(1.f - e, 1.f + e);
}
// ---- tf32 helpers ----
__device__ __forceinline__ u32 f2tf(float f) {
    u32 u; asm("cvt.rna.tf32.f32 %0, %1;" : "=r"(u) : "f"(f)); return u;
}
__device__ __forceinline__ void mma_tf32(float* c, u32 a0, u32 a1, u32 a2, u32 a3,
                                         u32 b0, u32 b1) {
    asm volatile("mma.sync.aligned.m16n8k8.row.col.f32.tf32.tf32.f32 "
        "{%0,%1,%2,%3}, {%4,%5,%6,%7}, {%8,%9}, {%0,%1,%2,%3};"
        : "+f"(c[0]), "+f"(c[1]), "+f"(c[2]), "+f"(c[3])
        : "r"(a0), "r"(a1), "r"(a2), "r"(a3), "r"(b0), "r"(b1));
}

// -------- device scratch --------
__device__ __align__(128) float g_msg[(size_t)N_EDGES * HID];   // 256 MB (CSR-ordered)
__device__ __align__(128) float g_agg[(size_t)N_NODES * HID];   // 25.6 MB
__device__ __align__(128) u32 g_W1frag[4 * 8 * 32 * 2];         // msg layer-1 B-frags
__device__ __align__(128) u32 g_W2frag[8 * 8 * 32 * 2];         // msg layer-2 B-frags
#define GRU_FRAG_U32 (8 * 24 * 32 * 2)                          // 12288
__device__ __align__(128) u32 g_WihFrag[GRU_FRAG_U32];          // gru B-frags (192 out)
__device__ __align__(128) u32 g_WhhFrag[GRU_FRAG_U32];
__device__ __align__(128) int g_count[N_NODES];                 // zeroed by scan after use
__device__ __align__(128) int g_rowstart[N_NODES + 1];
__device__ __align__(128) int g_cursor[N_NODES];
__device__ __align__(128) int g_src[N_EDGES];
__device__ __align__(128) int g_eperm[N_EDGES];

// -------- CSR build: histogram --------
__global__ __launch_bounds__(256) void hist_kernel(const int* __restrict__ eidx) {
    int t = blockIdx.x * 256 + threadIdx.x;
    if (t >= N_EDGES) return;
    int dst = eidx[t];
    if ((unsigned)dst < N_NODES) atomicAdd(&g_count[dst], 1);
}

// -------- CSR build: scan; builds all tf32 weight fragments; re-zeroes g_count
__global__ __launch_bounds__(1024) void scan_kernel(
    const float* __restrict__ W1, const float* __restrict__ W2,
    const float* __restrict__ Wih, const float* __restrict__ Whh)
{
    // B-frag layout (m16n8k8, row.col): lane = g*4+t; b0 = (k = kk*8+t, n = nt*8+g),
    // b1 = same with k+4. Stored at [((kk*NT + nt)*32 + lane)*2 + {0,1}].
    {
        int p = threadIdx.x;                 // 1024 = 4 kk * 8 nt * 32 lanes
        int lane = p & 31, nt = (p >> 5) & 7, kk = p >> 8;
        int gg = lane >> 2, tt = lane & 3;
        int n = nt * 8 + gg;
        g_W1frag[p * 2]     = f2tf(W1[n * EDIM + kk * 8 + tt]);
        g_W1frag[p * 2 + 1] = f2tf(W1[n * EDIM + kk * 8 + tt + 4]);
    }
    for (int p = threadIdx.x; p < 2048; p += 1024) {             // 8 kk * 8 nt * 32
        int lane = p & 31, nt = (p >> 5) & 7, kk = p >> 8;
        int gg = lane >> 2, tt = lane & 3;
        int n = nt * 8 + gg;
        g_W2frag[p * 2]     = f2tf(W2[n * HID + kk * 8 + tt]);
        g_W2frag[p * 2 + 1] = f2tf(W2[n * HID + kk * 8 + tt + 4]);
    }
    for (int p = threadIdx.x; p < 6144; p += 1024) {             // 8 kk * 24 nt * 32
        int lane = p & 31;
        int knt = p >> 5;                    // kk*24 + nt
        int kk = knt / 24, nt = knt % 24;
        int gg = lane >> 2, tt = lane & 3;
        int n = nt * 8 + gg;                 // 0..191
        g_WihFrag[p * 2]     = f2tf(Wih[n * HID + kk * 8 + tt]);
        g_WihFrag[p * 2 + 1] = f2tf(Wih[n * HID + kk * 8 + tt + 4]);
        g_WhhFrag[p * 2]     = f2tf(Whh[n * HID + kk * 8 + tt]);
        g_WhhFrag[p * 2 + 1] = f2tf(Whh[n * HID + kk * 8 + tt + 4]);
    }

    __shared__ int s[1024];
    const int T = 1024;
    const int tid = threadIdx.x;
    const int chunk = (N_NODES + T - 1) / T;
    const int start = tid * chunk;
    int sum = 0;
    for (int i = 0; i < chunk; ++i) {
        int idx = start + i;
        if (idx < N_NODES) sum += g_count[idx];
    }
    s[tid] = sum;
    __syncthreads();
    for (int off = 1; off < T; off <<= 1) {
        int v = 0;
        if (tid >= off) v = s[tid - off];
        __syncthreads();
        if (tid >= off) s[tid] += v;
        __syncthreads();
    }
    int run = (tid == 0) ? 0 : s[tid - 1];
    for (int i = 0; i < chunk; ++i) {
        int idx = start + i;
        if (idx < N_NODES) {
            g_rowstart[idx] = run;
            g_cursor[idx]   = run;
            run += g_count[idx];
            g_count[idx] = 0;
        }
    }
    if (tid == T - 1) g_rowstart[N_NODES] = run;
}

// -------- CSR build: bucket placement --------
__global__ __launch_bounds__(256) void place_kernel(const int* __restrict__ eidx) {
    int t = blockIdx.x * 256 + threadIdx.x;
    if (t >= N_EDGES) return;
    int dst = eidx[t];
    int src = eidx[N_EDGES + t];
    if ((unsigned)dst >= N_NODES || (unsigned)src >= N_NODES) { g_eperm[t] = 0; return; }
    int pos = atomicAdd(&g_cursor[dst], 1);
    g_src[pos] = src;
    g_eperm[t] = pos;
}

// -------- K1: msg MLP via tf32 mma.sync (R13 winner, unchanged) --------------
#define MSG_PITCH 68
#define MSG_SMEM_WORDS (256 * MSG_PITCH + 2048 + 4096)
#define MSG_SMEM_BYTES (MSG_SMEM_WORDS * 4)   // 94,208 B -> 2 CTAs/SM

__global__ __launch_bounds__(256, 2) void msg_kernel(
    const float* __restrict__ ea,
    const float* __restrict__ b1, const float* __restrict__ b2)
{
    extern __shared__ u32 smu[];
    u32* hidS = smu;
    u32* f1   = smu + 256 * MSG_PITCH;
    u32* f2   = f1 + 2048;

    const int tid = threadIdx.x;
    const int w = tid >> 5;
    const int lane = tid & 31;
    const int g = lane >> 2, t = lane & 3;
    const int eb = blockIdx.x * 256;

    for (int i = tid; i < 2048; i += 256) f1[i] = g_W1frag[i];
    for (int i = tid; i < 4096; i += 256) f2[i] = g_W2frag[i];
    __syncthreads();

    const int ebase = eb + w * 32;

    #pragma unroll 1
    for (int m = 0; m < 2; ++m) {
        const int e0 = ebase + m * 16;
        const int r0 = e0 + g, r1 = e0 + g + 8;
        const int lr0 = w * 32 + m * 16 + g, lr1 = lr0 + 8;
        float c[8][4];

        #pragma unroll
        for (int nt = 0; nt < 8; ++nt) {
            float blo = __ldg(&b1[nt * 8 + 2 * t]);
            float bhi = __ldg(&b1[nt * 8 + 2 * t + 1]);
            c[nt][0] = blo; c[nt][1] = bhi; c[nt][2] = blo; c[nt][3] = bhi;
        }
        #pragma unroll
        for (int kk = 0; kk < 4; ++kk) {
            float fa0 = (r0 < N_EDGES) ? __ldg(&ea[(size_t)r0 * EDIM + kk * 8 + t])     : 0.f;
            float fa1 = (r1 < N_EDGES) ? __ldg(&ea[(size_t)r1 * EDIM + kk * 8 + t])     : 0.f;
            float fa2 = (r0 < N_EDGES) ? __ldg(&ea[(size_t)r0 * EDIM + kk * 8 + t + 4]) : 0.f;
            float fa3 = (r1 < N_EDGES) ? __ldg(&ea[(size_t)r1 * EDIM + kk * 8 + t + 4]) : 0.f;
            u32 a0 = f2tf(fa0), a1 = f2tf(fa1), a2 = f2tf(fa2), a3 = f2tf(fa3);
            #pragma unroll
            for (int nt = 0; nt < 8; ++nt) {
                uint2 b = *reinterpret_cast<const uint2*>(&f1[((kk * 8 + nt) * 32 + lane) * 2]);
                mma_tf32(c[nt], a0, a1, a2, a3, b.x, b.y);
            }
        }
        #pragma unroll
        for (int nt = 0; nt < 8; ++nt) {
            u32 v00 = f2tf(fmaxf(c[nt][0], 0.f)), v01 = f2tf(fmaxf(c[nt][1], 0.f));
            u32 v10 = f2tf(fmaxf(c[nt][2], 0.f)), v11 = f2tf(fmaxf(c[nt][3], 0.f));
            *reinterpret_cast<uint2*>(&hidS[lr0 * MSG_PITCH + nt * 8 + 2 * t]) = make_uint2(v00, v01);
            *reinterpret_cast<uint2*>(&hidS[lr1 * MSG_PITCH + nt * 8 + 2 * t]) = make_uint2(v10, v11);
        }
        __syncwarp();

        #pragma unroll
        for (int nt = 0; nt < 8; ++nt) {
            float blo = __ldg(&b2[nt * 8 + 2 * t]);
            float bhi = __ldg(&b2[nt * 8 + 2 * t + 1]);
            c[nt][0] = blo; c[nt][1] = bhi; c[nt][2] = blo; c[nt][3] = bhi;
        }
        #pragma unroll
        for (int kk = 0; kk < 8; ++kk) {
            u32 a0 = hidS[lr0 * MSG_PITCH + kk * 8 + t];
            u32 a1 = hidS[lr1 * MSG_PITCH + kk * 8 + t];
            u32 a2 = hidS[lr0 * MSG_PITCH + kk * 8 + t + 4];
            u32 a3 = hidS[lr1 * MSG_PITCH + kk * 8 + t + 4];
            #pragma unroll
            for (int nt = 0; nt < 8; ++nt) {
                uint2 b = *reinterpret_cast<const uint2*>(&f2[((kk * 8 + nt) * 32 + lane) * 2]);
                mma_tf32(c[nt], a0, a1, a2, a3, b.x, b.y);
            }
        }
        int slot0 = (r0 < N_EDGES) ? __ldg(&g_eperm[r0]) : 0;
        int slot1 = (r1 < N_EDGES) ? __ldg(&g_eperm[r1]) : 0;
        #pragma unroll
        for (int nt = 0; nt < 8; ++nt) {
            if (r0 < N_EDGES)
                *reinterpret_cast<float2*>(&g_msg[(size_t)slot0 * HID + nt * 8 + 2 * t]) =
                    make_float2(c[nt][0], c[nt][1]);
            if (r1 < N_EDGES)
                *reinterpret_cast<float2*>(&g_msg[(size_t)slot1 * HID + nt * 8 + 2 * t]) =
                    make_float2(c[nt][2], c[nt][3]);
        }
        __syncwarp();
    }
}

// -------- K2: gather aggregation (unchanged) ---------------------------------
__global__ __launch_bounds__(256) void gather_kernel(const float* __restrict__ h) {
    int t = blockIdx.x * 256 + threadIdx.x;
    int n = t >> 4;
    int q = t & 15;
    if (n >= N_NODES) return;
    int p  = g_rowstart[n];
    int re = g_rowstart[n + 1];
    float4 acc = make_float4(0.f, 0.f, 0.f, 0.f);
    for (; p + 1 < re; p += 2) {
        float4 m0 = __ldcs(reinterpret_cast<const float4*>(&g_msg[(size_t)p * HID + q * 4]));
        float4 m1 = __ldcs(reinterpret_cast<const float4*>(&g_msg[(size_t)(p + 1) * HID + q * 4]));
        int s0 = __ldg(&g_src[p]);
        int s1 = __ldg(&g_src[p + 1]);
        float4 h0 = __ldg(reinterpret_cast<const float4*>(&h[(size_t)s0 * HID + q * 4]));
        float4 h1 = __ldg(reinterpret_cast<const float4*>(&h[(size_t)s1 * HID + q * 4]));
        acc.x += m0.x * h0.x; acc.y += m0.y * h0.y; acc.z += m0.z * h0.z; acc.w += m0.w * h0.w;
        acc.x += m1.x * h1.x; acc.y += m1.y * h1.y; acc.z += m1.z * h1.z; acc.w += m1.w * h1.w;
    }
    if (p < re) {
        float4 m = __ldcs(reinterpret_cast<const float4*>(&g_msg[(size_t)p * HID + q * 4]));
        int s = __ldg(&g_src[p]);
        float4 hv = __ldg(reinterpret_cast<const float4*>(&h[(size_t)s * HID + q * 4]));
        acc.x += m.x * hv.x; acc.y += m.y * hv.y; acc.z += m.z * hv.z; acc.w += m.w * hv.w;
    }
    *reinterpret_cast<float4*>(&g_agg[(size_t)n * HID + q * 4]) = acc;
}

// -------- K3: GRU via tf32 mma with A-residual compensation ------------------
// Persistent 152 CTAs x 512 threads; 64-node tiles. Warp w: m-tile = w&3
// (16 nodes), output group nh = w>>2 (6 nt of 8 outputs = 48 of 192 gates).
// GEMM1 (agg x Wih^T) and GEMM2 (h x Whh^T) -> smem [64][GP]; fp32 epilogue.
// A-residual: a = big + small (2 mma) so only weight truncation (~1.4e-4 rms)
// remains -- bounds error growth through the 4-step h feedback.
#define GP 196
#define GRU_SMEM_BYTES (2 * GRU_FRAG_U32 * 4 + 2 * 64 * GP * 4)   // 198,656 B

__global__ __launch_bounds__(512) void gru_kernel(
    const float* __restrict__ bih, const float* __restrict__ bhh,
    float* __restrict__ h)
{
    extern __shared__ u32 smu[];
    u32* fIH = smu;
    u32* fHH = smu + GRU_FRAG_U32;
    float* sGi = reinterpret_cast<float*>(smu + 2 * GRU_FRAG_U32);  // [64][GP]
    float* sGh = sGi + 64 * GP;

    const int tid = threadIdx.x;
    const int w = tid >> 5;
    const int lane = tid & 31;
    const int g = lane >> 2, t = lane & 3;
    const int m = w & 3;         // m-tile (16 nodes)
    const int nh = w >> 2;       // output group (6 nt)
    const int d = tid & 63;      // epilogue dim

    for (int i = tid; i < GRU_FRAG_U32; i += 512) { fIH[i] = g_WihFrag[i]; fHH[i] = g_WhhFrag[i]; }
    const float bi_r = __ldg(&bih[d]), bi_z = __ldg(&bih[64 + d]), bi_n = __ldg(&bih[128 + d]);
    const float bh_r = __ldg(&bhh[d]), bh_z = __ldg(&bhh[64 + d]), bh_n = __ldg(&bhh[128 + d]);
    __syncthreads();

    const int ntiles = (N_NODES + 63) / 64;   // 1563
    for (int tile = blockIdx.x; tile < ntiles; tile += gridDim.x) {
        const int nb = tile * 64;
        const int r0 = nb + m * 16 + g, r1 = r0 + 8;
        const bool v0 = r0 < N_NODES, v1 = r1 < N_NODES;

        // ---- GEMM1: Gi = agg x Wih^T ----
        float c[6][4];
        #pragma unroll
        for (int j = 0; j < 6; ++j) { c[j][0] = c[j][1] = c[j][2] = c[j][3] = 0.f; }
        #pragma unroll
        for (int kk = 0; kk < 8; ++kk) {
            float fa0 = v0 ? __ldg(&g_agg[(size_t)r0 * HID + kk * 8 + t])     : 0.f;
            float fa1 = v1 ? __ldg(&g_agg[(size_t)r1 * HID + kk * 8 + t])     : 0.f;
            float fa2 = v0 ? __ldg(&g_agg[(size_t)r0 * HID + kk * 8 + t + 4]) : 0.f;
            float fa3 = v1 ? __ldg(&g_agg[(size_t)r1 * HID + kk * 8 + t + 4]) : 0.f;
            u32 A0 = f2tf(fa0), A1 = f2tf(fa1), A2 = f2tf(fa2), A3 = f2tf(fa3);
            u32 S0 = f2tf(fa0 - __uint_as_float(A0));
            u32 S1 = f2tf(fa1 - __uint_as_float(A1));
            u32 S2 = f2tf(fa2 - __uint_as_float(A2));
            u32 S3 = f2tf(fa3 - __uint_as_float(A3));
            #pragma unroll
            for (int j = 0; j < 6; ++j) {
                uint2 b = *reinterpret_cast<const uint2*>(&fIH[((kk * 24 + nh * 6 + j) * 32 + lane) * 2]);
                mma_tf32(c[j], A0, A1, A2, A3, b.x, b.y);
                mma_tf32(c[j], S0, S1, S2, S3, b.x, b.y);
            }
        }
        #pragma unroll
        for (int j = 0; j < 6; ++j) {
            int n8 = (nh * 6 + j) * 8 + 2 * t;
            *reinterpret_cast<float2*>(&sGi[(m * 16 + g) * GP + n8])     = make_float2(c[j][0], c[j][1]);
            *reinterpret_cast<float2*>(&sGi[(m * 16 + g + 8) * GP + n8]) = make_float2(c[j][2], c[j][3]);
        }

        // ---- GEMM2: Gh = h x Whh^T ----
        #pragma unroll
        for (int j = 0; j < 6; ++j) { c[j][0] = c[j][1] = c[j][2] = c[j][3] = 0.f; }
        #pragma unroll
        for (int kk = 0; kk < 8; ++kk) {
            float fa0 = v0 ? __ldg(&h[(size_t)r0 * HID + kk * 8 + t])     : 0.f;
            float fa1 = v1 ? __ldg(&h[(size_t)r1 * HID + kk * 8 + t])     : 0.f;
            float fa2 = v0 ? __ldg(&h[(size_t)r0 * HID + kk * 8 + t + 4]) : 0.f;
            float fa3 = v1 ? __ldg(&h[(size_t)r1 * HID + kk * 8 + t + 4]) : 0.f;
            u32 A0 = f2tf(fa0), A1 = f2tf(fa1), A2 = f2tf(fa2), A3 = f2tf(fa3);
            u32 S0 = f2tf(fa0 - __uint_as_float(A0));
            u32 S1 = f2tf(fa1 - __uint_as_float(A1));
            u32 S2 = f2tf(fa2 - __uint_as_float(A2));
            u32 S3 = f2tf(fa3 - __uint_as_float(A3));
            #pragma unroll
            for (int j = 0; j < 6; ++j) {
                uint2 b = *reinterpret_cast<const uint2*>(&fHH[((kk * 24 + nh * 6 + j) * 32 + lane) * 2]);
                mma_tf32(c[j], A0, A1, A2, A3, b.x, b.y);
                mma_tf32(c[j], S0, S1, S2, S3, b.x, b.y);
            }
        }
        #pragma unroll
        for (int j = 0; j < 6; ++j) {
            int n8 = (nh * 6 + j) * 8 + 2 * t;
            *reinterpret_cast<float2*>(&sGh[(m * 16 + g) * GP + n8])     = make_float2(c[j][0], c[j][1]);
            *reinterpret_cast<float2*>(&sGh[(m * 16 + g + 8) * GP + n8]) = make_float2(c[j][2], c[j][3]);
        }
        __syncthreads();

        // ---- epilogue: elementwise GRU, coalesced ----
        #pragma unroll
        for (int it = 0; it < 8; ++it) {
            int node = it * 8 + (tid >> 6);
            if (nb + node < N_NODES) {
                float ir = sGi[node * GP + d];
                float iz = sGi[node * GP + 64 + d];
                float in_ = sGi[node * GP + 128 + d];
                float hr = sGh[node * GP + d];
                float hz = sGh[node * GP + 64 + d];
                float hn = sGh[node * GP + 128 + d];
                float rv = fsigmoid(ir + hr + bi_r + bh_r);
                float zv = fsigmoid(iz + hz + bi_z + bh_z);
                float nn = ftanh(in_ + bi_n + rv * (hn + bh_n));
                float hp = h[(size_t)(nb + node) * HID + d];
                h[(size_t)(nb + node) * HID + d] = (1.f - zv) * nn + zv * hp;
            }
        }
        __syncthreads();
    }
}

// -------- launch --------
extern "C" void kernel_launch(void* const* d_in, const int* in_sizes, int n_in,
                              void* d_out, int out_size)
{
    const float* h0   = (const float*)d_in[0];
    const float* ea   = (const float*)d_in[1];
    const int*   eidx = (const int*)d_in[2];     // int64 inputs arrive as int32
    const float* W1   = (const float*)d_in[3];
    const float* b1   = (const float*)d_in[4];
    const float* W2   = (const float*)d_in[5];
    const float* b2   = (const float*)d_in[6];
    const float* Wih  = (const float*)d_in[7];
    const float* bih  = (const float*)d_in[8];
    const float* Whh  = (const float*)d_in[9];
    const float* bhh  = (const float*)d_in[10];
    float* h = (float*)d_out;

    cudaFuncSetAttribute(gru_kernel, cudaFuncAttributeMaxDynamicSharedMemorySize,
                         GRU_SMEM_BYTES);
    cudaFuncSetAttribute(msg_kernel, cudaFuncAttributeMaxDynamicSharedMemorySize,
                         MSG_SMEM_BYTES);

    cudaMemcpyAsync(h, h0, (size_t)N_NODES * HID * sizeof(float),
                    cudaMemcpyDeviceToDevice, 0);

    // CSR build; g_count re-zeroed inside scan_kernel
    hist_kernel<<<(N_EDGES + 255) / 256, 256>>>(eidx);
    scan_kernel<<<1, 1024>>>(W1, W2, Wih, Whh);
    place_kernel<<<(N_EDGES + 255) / 256, 256>>>(eidx);

    msg_kernel<<<(N_EDGES + 255) / 256, 256, MSG_SMEM_BYTES>>>(ea, b1, b2);

    for (int s = 0; s < NSTEPS; ++s) {
        gather_kernel<<<(N_NODES * 16 + 255) / 256, 256>>>(h);
        gru_kernel<<<152, 512, GRU_SMEM_BYTES>>>(bih, bhh, h);
    }
}